// round 1
// baseline (speedup 1.0000x reference)
#include <cuda_runtime.h>
#include <math.h>

#define SEQ     2048
#define DIM     4096
#define NH      32
#define NKV     8
#define HD      128
#define WINDOW  1024
#define QDIM    (NH * HD)    // 4096
#define KVDIM   (NKV * HD)   // 1024

// Scratch (allocation-free: __device__ globals)
__device__ float g_q[SEQ * QDIM];    // 32 MB
__device__ float g_k[SEQ * KVDIM];   // 8 MB
__device__ float g_v[SEQ * KVDIM];   // 8 MB
__device__ float g_o[SEQ * QDIM];    // 32 MB

// ---------------------------------------------------------------------------
// Tiled NT GEMM: C[M,N] = A[M,K] * B[N,K]^T   (both row-major, K contiguous)
// 64x64 block tile, BK=16, 256 threads, 4x4 register tile per thread.
// All dims are multiples of tile sizes for this problem -> no bounds checks.
// ---------------------------------------------------------------------------
#define BM 64
#define BN 64
#define BKK 16

__global__ __launch_bounds__(256) void gemm_nt_kernel(
    const float* __restrict__ A, const float* __restrict__ B,
    float* __restrict__ C, int M, int N, int K)
{
    __shared__ float As[BM][BKK + 4];
    __shared__ float Bs[BN][BKK + 4];

    const int tid  = threadIdx.x;
    const int bm   = blockIdx.y * BM;
    const int bn   = blockIdx.x * BN;
    const int lrow = tid >> 2;          // 0..63
    const int lcol = (tid & 3) * 4;     // 0,4,8,12
    const int ty   = tid >> 4;          // 0..15 (m group)
    const int tx   = tid & 15;          // 0..15 (n group)

    float acc[4][4];
#pragma unroll
    for (int i = 0; i < 4; i++)
#pragma unroll
        for (int j = 0; j < 4; j++) acc[i][j] = 0.0f;

    for (int k0 = 0; k0 < K; k0 += BKK) {
        float4 a4 = *(const float4*)(A + (size_t)(bm + lrow) * K + k0 + lcol);
        float4 b4 = *(const float4*)(B + (size_t)(bn + lrow) * K + k0 + lcol);
        *(float4*)&As[lrow][lcol] = a4;
        *(float4*)&Bs[lrow][lcol] = b4;
        __syncthreads();

#pragma unroll
        for (int kk = 0; kk < BKK; kk++) {
            float ar[4], br[4];
#pragma unroll
            for (int i = 0; i < 4; i++) ar[i] = As[ty * 4 + i][kk];
#pragma unroll
            for (int j = 0; j < 4; j++) br[j] = Bs[tx * 4 + j][kk];
#pragma unroll
            for (int i = 0; i < 4; i++)
#pragma unroll
                for (int j = 0; j < 4; j++) acc[i][j] += ar[i] * br[j];
        }
        __syncthreads();
    }

#pragma unroll
    for (int i = 0; i < 4; i++) {
        float* crow = C + (size_t)(bm + ty * 4 + i) * N + bn + tx * 4;
#pragma unroll
        for (int j = 0; j < 4; j++) crow[j] = acc[i][j];
    }
}

// ---------------------------------------------------------------------------
// RoPE (interleaved pairs): one thread per (s, h, pair)
// t layout: [S, H, HD] contiguous. cos/sin: [S, HD/2]
// ---------------------------------------------------------------------------
__global__ void rope_kernel(float* __restrict__ t,
                            const float* __restrict__ cosb,
                            const float* __restrict__ sinb, int H)
{
    int idx = blockIdx.x * blockDim.x + threadIdx.x;
    int total = SEQ * H * (HD / 2);
    if (idx >= total) return;
    int p = idx % (HD / 2);
    int h = (idx / (HD / 2)) % H;
    int s = idx / ((HD / 2) * H);

    float c  = cosb[s * (HD / 2) + p];
    float sn = sinb[s * (HD / 2) + p];
    float* base = t + ((size_t)s * H + h) * HD + 2 * p;
    float t0 = base[0], t1 = base[1];
    base[0] = t0 * c - t1 * sn;
    base[1] = t0 * sn + t1 * c;
}

// ---------------------------------------------------------------------------
// Sliding-window causal GQA attention, one warp per (query, head).
// Online softmax; each lane owns 4 consecutive dims (float4).
// ---------------------------------------------------------------------------
__global__ __launch_bounds__(256) void attn_kernel(
    const float* __restrict__ q, const float* __restrict__ k,
    const float* __restrict__ v, float* __restrict__ o)
{
    int gwarp = (blockIdx.x * blockDim.x + threadIdx.x) >> 5;
    int lane  = threadIdx.x & 31;
    if (gwarp >= SEQ * NH) return;

    int h = gwarp % NH;
    int s = gwarp / NH;
    int kvh = h / (NH / NKV);

    const float scale = 0.08838834764831845f; // 1/sqrt(128)
    float4 qv = *(const float4*)(q + ((size_t)s * NH + h) * HD + lane * 4);
    qv.x *= scale; qv.y *= scale; qv.z *= scale; qv.w *= scale;

    float m = -INFINITY, l = 0.0f;
    float4 acc = make_float4(0.f, 0.f, 0.f, 0.f);

    int j0 = s - (WINDOW - 1);
    if (j0 < 0) j0 = 0;

    for (int j = j0; j <= s; j++) {
        const float* kbase = k + ((size_t)j * NKV + kvh) * HD + lane * 4;
        float4 kv4 = *(const float4*)kbase;
        float d = qv.x * kv4.x + qv.y * kv4.y + qv.z * kv4.z + qv.w * kv4.w;
#pragma unroll
        for (int off = 16; off; off >>= 1)
            d += __shfl_xor_sync(0xffffffffu, d, off);

        float mn = fmaxf(m, d);
        float alpha = __expf(m - mn);   // 0 on first iter (m = -inf)
        float p = __expf(d - mn);
        l = l * alpha + p;

        const float* vbase = v + ((size_t)j * NKV + kvh) * HD + lane * 4;
        float4 vv = *(const float4*)vbase;
        acc.x = acc.x * alpha + p * vv.x;
        acc.y = acc.y * alpha + p * vv.y;
        acc.z = acc.z * alpha + p * vv.z;
        acc.w = acc.w * alpha + p * vv.w;
        m = mn;
    }

    float inv = 1.0f / l;
    float4 outv = make_float4(acc.x * inv, acc.y * inv, acc.z * inv, acc.w * inv);
    *(float4*)(o + ((size_t)s * NH + h) * HD + lane * 4) = outv;
}

// ---------------------------------------------------------------------------
// Launch
// ---------------------------------------------------------------------------
extern "C" void kernel_launch(void* const* d_in, const int* in_sizes, int n_in,
                              void* d_out, int out_size)
{
    const float* x    = (const float*)d_in[0];
    const float* wq   = (const float*)d_in[1];
    const float* wk   = (const float*)d_in[2];
    const float* wv   = (const float*)d_in[3];
    const float* wo   = (const float*)d_in[4];
    const float* cosb = (const float*)d_in[5];
    const float* sinb = (const float*)d_in[6];
    float* out = (float*)d_out;

    float *q, *k, *v, *o;
    cudaGetSymbolAddress((void**)&q, g_q);
    cudaGetSymbolAddress((void**)&k, g_k);
    cudaGetSymbolAddress((void**)&v, g_v);
    cudaGetSymbolAddress((void**)&o, g_o);

    // QKV projections
    {
        dim3 gridQ(QDIM / BN, SEQ / BM);
        gemm_nt_kernel<<<gridQ, 256>>>(x, wq, q, SEQ, QDIM, DIM);
        dim3 gridK(KVDIM / BN, SEQ / BM);
        gemm_nt_kernel<<<gridK, 256>>>(x, wk, k, SEQ, KVDIM, DIM);
        gemm_nt_kernel<<<gridK, 256>>>(x, wv, v, SEQ, KVDIM, DIM);
    }

    // RoPE on q and k
    {
        int totq = SEQ * NH * (HD / 2);
        rope_kernel<<<(totq + 255) / 256, 256>>>(q, cosb, sinb, NH);
        int totk = SEQ * NKV * (HD / 2);
        rope_kernel<<<(totk + 255) / 256, 256>>>(k, cosb, sinb, NKV);
    }

    // Attention: one warp per (s, h)
    {
        int warps = SEQ * NH;
        int threads = warps * 32;
        attn_kernel<<<(threads + 255) / 256, 256>>>(q, k, v, o);
    }

    // Output projection
    {
        dim3 gridO(DIM / BN, SEQ / BM);
        gemm_nt_kernel<<<gridO, 256>>>(o, wo, out, SEQ, DIM, QDIM);
    }
}

// round 2
// speedup vs baseline: 3.1571x; 3.1571x over previous
#include <cuda_runtime.h>
#include <cuda_bf16.h>
#include <math.h>
#include <stdint.h>

#define SEQ     2048
#define DIM     4096
#define NH      32
#define NKV     8
#define HD      128
#define WINDOW  1024
#define QDIM    (NH * HD)    // 4096
#define KVDIM   (NKV * HD)   // 1024
#define K3      (3 * DIM)    // 12288 (split-K for all GEMMs; DIM == QDIM)

// ---------------------------------------------------------------------------
// Scratch (__device__ globals; allocation-free)
// ---------------------------------------------------------------------------
__device__ float g_q[SEQ * QDIM];
__device__ float g_k[SEQ * KVDIM];
__device__ float g_v[SEQ * KVDIM];
__device__ float g_o[SEQ * QDIM];

__device__ __nv_bfloat16 g_xs [SEQ  * K3];   // x   split (A-side: hi|lo|hi)
__device__ __nv_bfloat16 g_os [SEQ  * K3];   // o   split (A-side)
__device__ __nv_bfloat16 g_wqs[QDIM * K3];   // wq  split (B-side: hi|hi|lo)
__device__ __nv_bfloat16 g_wks[KVDIM * K3];
__device__ __nv_bfloat16 g_wvs[KVDIM * K3];
__device__ __nv_bfloat16 g_wos[DIM  * K3];

// ---------------------------------------------------------------------------
// fp32 -> bf16 hi/lo split conversion
// A-side layout per row: [hi(0..K) | lo(K..2K) | hi(2K..3K)]
// B-side layout per row: [hi(0..K) | hi(K..2K) | lo(2K..3K)]
// ---------------------------------------------------------------------------
__global__ void convert_split_kernel(const float* __restrict__ src,
                                     __nv_bfloat16* __restrict__ dst,
                                     int rows, int K, int a_side)
{
    int idx = blockIdx.x * blockDim.x + threadIdx.x;
    if (idx >= rows * K) return;
    int r = idx / K;
    int c = idx - r * K;
    float a = src[idx];
    __nv_bfloat16 hi = __float2bfloat16(a);
    __nv_bfloat16 lo = __float2bfloat16(a - __bfloat162float(hi));
    __nv_bfloat16* d = dst + (size_t)r * (3 * K) + c;
    if (a_side) { d[0] = hi; d[K] = lo; d[2 * K] = hi; }
    else        { d[0] = hi; d[K] = hi; d[2 * K] = lo; }
}

// ---------------------------------------------------------------------------
// bf16 NT GEMM: C[M,N] (fp32) = A[M,K'] * B[N,K']^T, fp32 accumulate.
// BM=128, BN=128, BK=32, 256 threads (8 warps: 2(M) x 4(N)), warp tile 64x32.
// mma.sync.m16n8k16.bf16, ldmatrix, cp.async double buffer.
// ---------------------------------------------------------------------------
#define BM 128
#define BN 128
#define BK 32
#define KP 40   // padded smem row stride (bf16 elems): conflict-free ldmatrix

__device__ __forceinline__ uint32_t smem_u32(const void* p) {
    return (uint32_t)__cvta_generic_to_shared(p);
}

__device__ __forceinline__ void cp_async16(uint32_t dst, const void* src) {
    asm volatile("cp.async.cg.shared.global [%0], [%1], 16;\n" :: "r"(dst), "l"(src));
}

__global__ __launch_bounds__(256, 2) void gemm_bf16_nt(
    const __nv_bfloat16* __restrict__ A, const __nv_bfloat16* __restrict__ B,
    float* __restrict__ C, int M, int N, int K)
{
    __shared__ __nv_bfloat16 As[2][BM][KP];
    __shared__ __nv_bfloat16 Bs[2][BN][KP];

    const int tid  = threadIdx.x;
    const int lane = tid & 31;
    const int w    = tid >> 5;
    const int bm   = blockIdx.y * BM;
    const int bn   = blockIdx.x * BN;
    const int warp_m = (w & 1) * 64;
    const int warp_n = (w >> 1) * 32;

    float acc[4][4][4];
#pragma unroll
    for (int i = 0; i < 4; i++)
#pragma unroll
        for (int j = 0; j < 4; j++)
#pragma unroll
            for (int r = 0; r < 4; r++) acc[i][j][r] = 0.0f;

    const int KB = K / BK;

    // stage loader: 128 rows x 32 bf16 = 512 x 16B chunks per matrix; 2 chunks/thread
    auto load_stage = [&](int kb, int buf) {
        int k0 = kb * BK;
#pragma unroll
        for (int i = 0; i < 2; i++) {
            int id  = tid + i * 256;       // 0..511
            int row = id >> 2;
            int c8  = (id & 3) * 8;        // bf16 col
            cp_async16(smem_u32(&As[buf][row][c8]),
                       A + (size_t)(bm + row) * K + k0 + c8);
            cp_async16(smem_u32(&Bs[buf][row][c8]),
                       B + (size_t)(bn + row) * K + k0 + c8);
        }
        asm volatile("cp.async.commit_group;\n");
    };

    load_stage(0, 0);

    for (int kb = 0; kb < KB; kb++) {
        int buf = kb & 1;
        if (kb + 1 < KB) {
            load_stage(kb + 1, buf ^ 1);
            asm volatile("cp.async.wait_group 1;\n");
        } else {
            asm volatile("cp.async.wait_group 0;\n");
        }
        __syncthreads();

#pragma unroll
        for (int ks = 0; ks < 2; ks++) {
            // A fragments: 4 m-tiles of 16x16
            uint32_t a_frag[4][4];
#pragma unroll
            for (int mt = 0; mt < 4; mt++) {
                uint32_t addr = smem_u32(
                    &As[buf][warp_m + mt * 16 + (lane & 15)][ks * 16 + (lane >> 4) * 8]);
                asm volatile(
                    "ldmatrix.sync.aligned.m8n8.x4.shared.b16 {%0,%1,%2,%3}, [%4];\n"
                    : "=r"(a_frag[mt][0]), "=r"(a_frag[mt][1]),
                      "=r"(a_frag[mt][2]), "=r"(a_frag[mt][3])
                    : "r"(addr));
            }
            // B fragments: 4 n-tiles of 8 (two x4 ldmatrix, each covers 2 n-tiles)
            uint32_t b_frag[4][2];
#pragma unroll
            for (int half = 0; half < 2; half++) {
                int nt0 = half * 2;
                int row = warp_n + nt0 * 8 + ((lane >> 4) & 1) * 8 + (lane & 7);
                int col = ks * 16 + ((lane >> 3) & 1) * 8;
                uint32_t addr = smem_u32(&Bs[buf][row][col]);
                asm volatile(
                    "ldmatrix.sync.aligned.m8n8.x4.shared.b16 {%0,%1,%2,%3}, [%4];\n"
                    : "=r"(b_frag[nt0][0]), "=r"(b_frag[nt0][1]),
                      "=r"(b_frag[nt0 + 1][0]), "=r"(b_frag[nt0 + 1][1])
                    : "r"(addr));
            }
#pragma unroll
            for (int mt = 0; mt < 4; mt++)
#pragma unroll
                for (int nt = 0; nt < 4; nt++) {
                    asm volatile(
                        "mma.sync.aligned.m16n8k16.row.col.f32.bf16.bf16.f32 "
                        "{%0,%1,%2,%3}, {%4,%5,%6,%7}, {%8,%9}, {%0,%1,%2,%3};\n"
                        : "+f"(acc[mt][nt][0]), "+f"(acc[mt][nt][1]),
                          "+f"(acc[mt][nt][2]), "+f"(acc[mt][nt][3])
                        : "r"(a_frag[mt][0]), "r"(a_frag[mt][1]),
                          "r"(a_frag[mt][2]), "r"(a_frag[mt][3]),
                          "r"(b_frag[nt][0]), "r"(b_frag[nt][1]));
                }
        }
        __syncthreads();
    }

    // Epilogue
    const int g   = lane >> 2;
    const int tig = lane & 3;
#pragma unroll
    for (int mt = 0; mt < 4; mt++) {
#pragma unroll
        for (int nt = 0; nt < 4; nt++) {
            float* c0 = C + (size_t)(bm + warp_m + mt * 16 + g) * N
                          + bn + warp_n + nt * 8 + tig * 2;
            float* c1 = c0 + 8 * (size_t)N;
            *(float2*)c0 = make_float2(acc[mt][nt][0], acc[mt][nt][1]);
            *(float2*)c1 = make_float2(acc[mt][nt][2], acc[mt][nt][3]);
        }
    }
}

// ---------------------------------------------------------------------------
// RoPE (interleaved pairs)
// ---------------------------------------------------------------------------
__global__ void rope_kernel(float* __restrict__ t,
                            const float* __restrict__ cosb,
                            const float* __restrict__ sinb, int H)
{
    int idx = blockIdx.x * blockDim.x + threadIdx.x;
    int total = SEQ * H * (HD / 2);
    if (idx >= total) return;
    int p = idx % (HD / 2);
    int h = (idx / (HD / 2)) % H;
    int s = idx / ((HD / 2) * H);

    float c  = cosb[s * (HD / 2) + p];
    float sn = sinb[s * (HD / 2) + p];
    float* base = t + ((size_t)s * H + h) * HD + 2 * p;
    float t0 = base[0], t1 = base[1];
    base[0] = t0 * c - t1 * sn;
    base[1] = t0 * sn + t1 * c;
}

// ---------------------------------------------------------------------------
// Sliding-window causal GQA attention, one warp per (query, head).
// Online softmax; 2-key unroll for ILP across the shuffle/exp chains.
// ---------------------------------------------------------------------------
__device__ __forceinline__ float warp_dot128(const float4& q, const float4& k) {
    float d = q.x * k.x + q.y * k.y + q.z * k.z + q.w * k.w;
#pragma unroll
    for (int off = 16; off; off >>= 1)
        d += __shfl_xor_sync(0xffffffffu, d, off);
    return d;
}

__global__ __launch_bounds__(256) void attn_kernel(
    const float* __restrict__ q, const float* __restrict__ k,
    const float* __restrict__ v, float* __restrict__ o)
{
    int gwarp = (blockIdx.x * blockDim.x + threadIdx.x) >> 5;
    int lane  = threadIdx.x & 31;
    if (gwarp >= SEQ * NH) return;

    int h = gwarp % NH;
    int s = gwarp / NH;
    int kvh = h / (NH / NKV);

    const float scale = 0.08838834764831845f; // 1/sqrt(128)
    float4 qv = *(const float4*)(q + ((size_t)s * NH + h) * HD + lane * 4);
    qv.x *= scale; qv.y *= scale; qv.z *= scale; qv.w *= scale;

    float m = -INFINITY, l = 0.0f;
    float4 acc = make_float4(0.f, 0.f, 0.f, 0.f);

    int j0 = s - (WINDOW - 1);
    if (j0 < 0) j0 = 0;
    int len = s - j0 + 1;
    int j = j0;

    const float* kb = k + (size_t)kvh * HD + lane * 4;
    const float* vb = v + (size_t)kvh * HD + lane * 4;

    if (len & 1) {
        float4 kv4 = *(const float4*)(kb + (size_t)j * KVDIM);
        float4 vv  = *(const float4*)(vb + (size_t)j * KVDIM);
        float d = warp_dot128(qv, kv4);
        float mn = fmaxf(m, d);
        float alpha = __expf(m - mn);
        float p = __expf(d - mn);
        l = l * alpha + p;
        acc.x = acc.x * alpha + p * vv.x;
        acc.y = acc.y * alpha + p * vv.y;
        acc.z = acc.z * alpha + p * vv.z;
        acc.w = acc.w * alpha + p * vv.w;
        m = mn;
        j++;
    }

    for (; j < s; j += 2) {
        float4 k0 = *(const float4*)(kb + (size_t)j * KVDIM);
        float4 k1 = *(const float4*)(kb + (size_t)(j + 1) * KVDIM);
        float4 v0 = *(const float4*)(vb + (size_t)j * KVDIM);
        float4 v1 = *(const float4*)(vb + (size_t)(j + 1) * KVDIM);

        float d0 = qv.x * k0.x + qv.y * k0.y + qv.z * k0.z + qv.w * k0.w;
        float d1 = qv.x * k1.x + qv.y * k1.y + qv.z * k1.z + qv.w * k1.w;
#pragma unroll
        for (int off = 16; off; off >>= 1) {
            d0 += __shfl_xor_sync(0xffffffffu, d0, off);
            d1 += __shfl_xor_sync(0xffffffffu, d1, off);
        }

        float mn = fmaxf(m, fmaxf(d0, d1));
        float alpha = __expf(m - mn);
        float p0 = __expf(d0 - mn);
        float p1 = __expf(d1 - mn);
        l = l * alpha + p0 + p1;
        acc.x = acc.x * alpha + p0 * v0.x + p1 * v1.x;
        acc.y = acc.y * alpha + p0 * v0.y + p1 * v1.y;
        acc.z = acc.z * alpha + p0 * v0.z + p1 * v1.z;
        acc.w = acc.w * alpha + p0 * v0.w + p1 * v1.w;
        m = mn;
    }

    float inv = 1.0f / l;
    *(float4*)(o + ((size_t)s * NH + h) * HD + lane * 4) =
        make_float4(acc.x * inv, acc.y * inv, acc.z * inv, acc.w * inv);
}

// ---------------------------------------------------------------------------
// Launch
// ---------------------------------------------------------------------------
extern "C" void kernel_launch(void* const* d_in, const int* in_sizes, int n_in,
                              void* d_out, int out_size)
{
    const float* x    = (const float*)d_in[0];
    const float* wq   = (const float*)d_in[1];
    const float* wk   = (const float*)d_in[2];
    const float* wv   = (const float*)d_in[3];
    const float* wo   = (const float*)d_in[4];
    const float* cosb = (const float*)d_in[5];
    const float* sinb = (const float*)d_in[6];
    float* out = (float*)d_out;

    float *q, *k, *v, *o;
    __nv_bfloat16 *xs, *os, *wqs, *wks, *wvs, *wos;
    cudaGetSymbolAddress((void**)&q, g_q);
    cudaGetSymbolAddress((void**)&k, g_k);
    cudaGetSymbolAddress((void**)&v, g_v);
    cudaGetSymbolAddress((void**)&o, g_o);
    cudaGetSymbolAddress((void**)&xs, g_xs);
    cudaGetSymbolAddress((void**)&os, g_os);
    cudaGetSymbolAddress((void**)&wqs, g_wqs);
    cudaGetSymbolAddress((void**)&wks, g_wks);
    cudaGetSymbolAddress((void**)&wvs, g_wvs);
    cudaGetSymbolAddress((void**)&wos, g_wos);

    const int T = 256;
    // split conversions
    convert_split_kernel<<<(SEQ * DIM + T - 1) / T, T>>>(x, xs, SEQ, DIM, 1);
    convert_split_kernel<<<(QDIM * DIM + T - 1) / T, T>>>(wq, wqs, QDIM, DIM, 0);
    convert_split_kernel<<<(KVDIM * DIM + T - 1) / T, T>>>(wk, wks, KVDIM, DIM, 0);
    convert_split_kernel<<<(KVDIM * DIM + T - 1) / T, T>>>(wv, wvs, KVDIM, DIM, 0);
    convert_split_kernel<<<(DIM * QDIM + T - 1) / T, T>>>(wo, wos, DIM, QDIM, 0);

    // QKV projections (bf16 split GEMM, K' = 12288)
    {
        dim3 gq(QDIM / BN, SEQ / BM);
        gemm_bf16_nt<<<gq, 256>>>(xs, wqs, q, SEQ, QDIM, K3);
        dim3 gkv(KVDIM / BN, SEQ / BM);
        gemm_bf16_nt<<<gkv, 256>>>(xs, wks, k, SEQ, KVDIM, K3);
        gemm_bf16_nt<<<gkv, 256>>>(xs, wvs, v, SEQ, KVDIM, K3);
    }

    // RoPE
    rope_kernel<<<(SEQ * NH * (HD / 2) + T - 1) / T, T>>>(q, cosb, sinb, NH);
    rope_kernel<<<(SEQ * NKV * (HD / 2) + T - 1) / T, T>>>(k, cosb, sinb, NKV);

    // Attention
    {
        int warps = SEQ * NH;
        attn_kernel<<<(warps * 32 + T - 1) / T, T>>>(q, k, v, o);
    }

    // o -> split, then output projection
    convert_split_kernel<<<(SEQ * QDIM + T - 1) / T, T>>>(o, os, SEQ, QDIM, 1);
    {
        dim3 go(DIM / BN, SEQ / BM);
        gemm_bf16_nt<<<go, 256>>>(os, wos, out, SEQ, DIM, K3);
    }
}

// round 3
// speedup vs baseline: 6.0966x; 1.9311x over previous
#include <cuda_runtime.h>
#include <cuda_bf16.h>
#include <math.h>
#include <stdint.h>

#define SEQ     2048
#define DIM     4096
#define NH      32
#define NKV     8
#define HD      128
#define WINDOW  1024
#define QDIM    (NH * HD)    // 4096
#define KVDIM   (NKV * HD)   // 1024
#define K3      (3 * DIM)    // 12288

// ---------------------------------------------------------------------------
// Scratch
// ---------------------------------------------------------------------------
__device__ float g_q[SEQ * QDIM];
__device__ float g_k[SEQ * KVDIM];
__device__ float g_v[SEQ * KVDIM];
__device__ float g_o[SEQ * QDIM];

__device__ __nv_bfloat16 g_xs [SEQ  * K3];
__device__ __nv_bfloat16 g_os [SEQ  * K3];
__device__ __nv_bfloat16 g_wqs[QDIM * K3];
__device__ __nv_bfloat16 g_wks[KVDIM * K3];
__device__ __nv_bfloat16 g_wvs[KVDIM * K3];
__device__ __nv_bfloat16 g_wos[DIM  * K3];

// attention operand splits (post-rope)
__device__ __nv_bfloat16 g_qh[SEQ * QDIM],  g_ql[SEQ * QDIM];
__device__ __nv_bfloat16 g_kh[SEQ * KVDIM], g_kl[SEQ * KVDIM];
__device__ __nv_bfloat16 g_vh[SEQ * KVDIM], g_vl[SEQ * KVDIM];

// ---------------------------------------------------------------------------
// helpers
// ---------------------------------------------------------------------------
__device__ __forceinline__ uint32_t smem_u32(const void* p) {
    return (uint32_t)__cvta_generic_to_shared(p);
}
__device__ __forceinline__ void cp_async16(uint32_t dst, const void* src) {
    asm volatile("cp.async.cg.shared.global [%0], [%1], 16;\n" :: "r"(dst), "l"(src));
}
__device__ __forceinline__ void mma16816(float* c, const uint32_t* a, const uint32_t* b) {
    asm volatile(
        "mma.sync.aligned.m16n8k16.row.col.f32.bf16.bf16.f32 "
        "{%0,%1,%2,%3}, {%4,%5,%6,%7}, {%8,%9}, {%0,%1,%2,%3};\n"
        : "+f"(c[0]), "+f"(c[1]), "+f"(c[2]), "+f"(c[3])
        : "r"(a[0]), "r"(a[1]), "r"(a[2]), "r"(a[3]), "r"(b[0]), "r"(b[1]));
}
__device__ __forceinline__ void ldsm4(uint32_t* r, uint32_t addr) {
    asm volatile("ldmatrix.sync.aligned.m8n8.x4.shared.b16 {%0,%1,%2,%3}, [%4];\n"
        : "=r"(r[0]), "=r"(r[1]), "=r"(r[2]), "=r"(r[3]) : "r"(addr));
}
__device__ __forceinline__ void ldsm4t(uint32_t* r, uint32_t addr) {
    asm volatile("ldmatrix.sync.aligned.m8n8.x4.trans.shared.b16 {%0,%1,%2,%3}, [%4];\n"
        : "=r"(r[0]), "=r"(r[1]), "=r"(r[2]), "=r"(r[3]) : "r"(addr));
}
__device__ __forceinline__ void split_pack(float p0, float p1, uint32_t& hi, uint32_t& lo) {
    __nv_bfloat16 h0 = __float2bfloat16(p0), h1 = __float2bfloat16(p1);
    hi = ((uint32_t)*(uint16_t*)&h1 << 16) | (uint32_t)*(uint16_t*)&h0;
    __nv_bfloat16 l0 = __float2bfloat16(p0 - __bfloat162float(h0));
    __nv_bfloat16 l1 = __float2bfloat16(p1 - __bfloat162float(h1));
    lo = ((uint32_t)*(uint16_t*)&l1 << 16) | (uint32_t)*(uint16_t*)&l0;
}

// ---------------------------------------------------------------------------
// fp32 -> bf16 hi/lo split for GEMM K-concat layout
// ---------------------------------------------------------------------------
__global__ void convert_split_kernel(const float* __restrict__ src,
                                     __nv_bfloat16* __restrict__ dst,
                                     int rows, int K, int a_side)
{
    int idx = blockIdx.x * blockDim.x + threadIdx.x;
    if (idx >= rows * K) return;
    int r = idx / K;
    int c = idx - r * K;
    float a = src[idx];
    __nv_bfloat16 hi = __float2bfloat16(a);
    __nv_bfloat16 lo = __float2bfloat16(a - __bfloat162float(hi));
    __nv_bfloat16* d = dst + (size_t)r * (3 * K) + c;
    if (a_side) { d[0] = hi; d[K] = lo; d[2 * K] = hi; }
    else        { d[0] = hi; d[K] = hi; d[2 * K] = lo; }
}

// fp32 -> (hi, lo) bf16, same layout, optional scale
__global__ void split2_kernel(const float* __restrict__ src,
                              __nv_bfloat16* __restrict__ hi,
                              __nv_bfloat16* __restrict__ lo,
                              int n, float scale)
{
    int i = blockIdx.x * blockDim.x + threadIdx.x;
    if (i >= n) return;
    float a = src[i] * scale;
    __nv_bfloat16 h = __float2bfloat16(a);
    hi[i] = h;
    lo[i] = __float2bfloat16(a - __bfloat162float(h));
}

// ---------------------------------------------------------------------------
// bf16 NT GEMM (unchanged from R2)
// ---------------------------------------------------------------------------
#define BM 128
#define BN 128
#define BK 32
#define KP 40

__global__ __launch_bounds__(256, 2) void gemm_bf16_nt(
    const __nv_bfloat16* __restrict__ A, const __nv_bfloat16* __restrict__ B,
    float* __restrict__ C, int M, int N, int K)
{
    __shared__ __nv_bfloat16 As[2][BM][KP];
    __shared__ __nv_bfloat16 Bs[2][BN][KP];

    const int tid  = threadIdx.x;
    const int lane = tid & 31;
    const int w    = tid >> 5;
    const int bm   = blockIdx.y * BM;
    const int bn   = blockIdx.x * BN;
    const int warp_m = (w & 1) * 64;
    const int warp_n = (w >> 1) * 32;

    float acc[4][4][4];
#pragma unroll
    for (int i = 0; i < 4; i++)
#pragma unroll
        for (int j = 0; j < 4; j++)
#pragma unroll
            for (int r = 0; r < 4; r++) acc[i][j][r] = 0.0f;

    const int KB = K / BK;

    auto load_stage = [&](int kb, int buf) {
        int k0 = kb * BK;
#pragma unroll
        for (int i = 0; i < 2; i++) {
            int id  = tid + i * 256;
            int row = id >> 2;
            int c8  = (id & 3) * 8;
            cp_async16(smem_u32(&As[buf][row][c8]),
                       A + (size_t)(bm + row) * K + k0 + c8);
            cp_async16(smem_u32(&Bs[buf][row][c8]),
                       B + (size_t)(bn + row) * K + k0 + c8);
        }
        asm volatile("cp.async.commit_group;\n");
    };

    load_stage(0, 0);

    for (int kb = 0; kb < KB; kb++) {
        int buf = kb & 1;
        if (kb + 1 < KB) {
            load_stage(kb + 1, buf ^ 1);
            asm volatile("cp.async.wait_group 1;\n");
        } else {
            asm volatile("cp.async.wait_group 0;\n");
        }
        __syncthreads();

#pragma unroll
        for (int ks = 0; ks < 2; ks++) {
            uint32_t a_frag[4][4];
#pragma unroll
            for (int mt = 0; mt < 4; mt++) {
                uint32_t addr = smem_u32(
                    &As[buf][warp_m + mt * 16 + (lane & 15)][ks * 16 + (lane >> 4) * 8]);
                ldsm4(a_frag[mt], addr);
            }
            uint32_t b_frag[4][2];
#pragma unroll
            for (int half = 0; half < 2; half++) {
                int nt0 = half * 2;
                int row = warp_n + nt0 * 8 + ((lane >> 4) & 1) * 8 + (lane & 7);
                int col = ks * 16 + ((lane >> 3) & 1) * 8;
                uint32_t r4[4];
                ldsm4(r4, smem_u32(&Bs[buf][row][col]));
                b_frag[nt0][0] = r4[0]; b_frag[nt0][1] = r4[1];
                b_frag[nt0 + 1][0] = r4[2]; b_frag[nt0 + 1][1] = r4[3];
            }
#pragma unroll
            for (int mt = 0; mt < 4; mt++)
#pragma unroll
                for (int nt = 0; nt < 4; nt++)
                    mma16816(acc[mt][nt], a_frag[mt], b_frag[nt]);
        }
        __syncthreads();
    }

    const int g   = lane >> 2;
    const int tig = lane & 3;
#pragma unroll
    for (int mt = 0; mt < 4; mt++) {
#pragma unroll
        for (int nt = 0; nt < 4; nt++) {
            float* c0 = C + (size_t)(bm + warp_m + mt * 16 + g) * N
                          + bn + warp_n + nt * 8 + tig * 2;
            float* c1 = c0 + 8 * (size_t)N;
            *(float2*)c0 = make_float2(acc[mt][nt][0], acc[mt][nt][1]);
            *(float2*)c1 = make_float2(acc[mt][nt][2], acc[mt][nt][3]);
        }
    }
}

// ---------------------------------------------------------------------------
// RoPE
// ---------------------------------------------------------------------------
__global__ void rope_kernel(float* __restrict__ t,
                            const float* __restrict__ cosb,
                            const float* __restrict__ sinb, int H)
{
    int idx = blockIdx.x * blockDim.x + threadIdx.x;
    int total = SEQ * H * (HD / 2);
    if (idx >= total) return;
    int p = idx % (HD / 2);
    int h = (idx / (HD / 2)) % H;
    int s = idx / ((HD / 2) * H);

    float c  = cosb[s * (HD / 2) + p];
    float sn = sinb[s * (HD / 2) + p];
    float* base = t + ((size_t)s * H + h) * HD + 2 * p;
    float t0 = base[0], t1 = base[1];
    base[0] = t0 * c - t1 * sn;
    base[1] = t0 * sn + t1 * c;
}

// ---------------------------------------------------------------------------
// Flash attention with bf16 mma + 3-term precision split.
// Block: (q-tile of 64 positions) x (2 heads sharing a kv head). M=128 rows.
// Key tiles of 64, double-buffered cp.async. 8 warps, warp = m16 x n64.
// ---------------------------------------------------------------------------
#define PDD 136   // padded smem row stride (bf16): conflict-free ldmatrix
#define ATT_SMEM ((2 * 128 * PDD + 2 * 4 * 64 * PDD) * 2)  // 208896 bytes

__global__ __launch_bounds__(256, 1) void attn_mma_kernel(
    const __nv_bfloat16* __restrict__ Qh, const __nv_bfloat16* __restrict__ Ql,
    const __nv_bfloat16* __restrict__ Kh, const __nv_bfloat16* __restrict__ Kl,
    const __nv_bfloat16* __restrict__ Vh, const __nv_bfloat16* __restrict__ Vl,
    float* __restrict__ O)
{
    extern __shared__ __nv_bfloat16 sm[];
    __nv_bfloat16* sQh = sm;                        // 128*PDD
    __nv_bfloat16* sQl = sQh + 128 * PDD;
    __nv_bfloat16* sKV = sQl + 128 * PDD;           // 2 bufs x 4 mats x 64*PDD

    const int tid  = threadIdx.x;
    const int lane = tid & 31;
    const int w    = tid >> 5;
    const int q0   = blockIdx.x * 64;
    const int kvh  = blockIdx.y >> 1;
    const int h0   = kvh * 4 + (blockIdx.y & 1) * 2;

    const int warp_row = w * 16;
    const int s_row0 = q0 + (warp_row & 63) + (lane >> 2);
    const int s_row1 = s_row0 + 8;
    const int h_out  = h0 + (warp_row >> 6);

    // ---- load Q (hi & lo), 128 rows x 128 cols bf16 ----
#pragma unroll
    for (int i = 0; i < 8; i++) {
        int id = tid + i * 256;
        int r = id >> 4, c8 = (id & 15) * 8;
        int s = q0 + (r & 63), h = h0 + (r >> 6);
        size_t g = ((size_t)s * NH + h) * HD + c8;
        cp_async16(smem_u32(sQh + r * PDD + c8), Qh + g);
        cp_async16(smem_u32(sQl + r * PDD + c8), Ql + g);
    }
    asm volatile("cp.async.commit_group;\n");

    // per-thread softmax state (rows s_row0, s_row1)
    float m0 = -1e30f, m1 = -1e30f, l0 = 0.f, l1 = 0.f;
    float o_acc[16][4];
#pragma unroll
    for (int i = 0; i < 16; i++)
#pragma unroll
        for (int r = 0; r < 4; r++) o_acc[i][r] = 0.f;

    int jlo = q0 - (WINDOW - 1); if (jlo < 0) jlo = 0;
    const int t0 = jlo >> 6, t1 = (q0 + 63) >> 6;

    auto load_kv = [&](int kt, int buf) {
        __nv_bfloat16* base = sKV + buf * 4 * 64 * PDD;
        __nv_bfloat16* bKh = base;
        __nv_bfloat16* bKl = base + 64 * PDD;
        __nv_bfloat16* bVh = base + 2 * 64 * PDD;
        __nv_bfloat16* bVl = base + 3 * 64 * PDD;
        int kt0 = kt << 6;
#pragma unroll
        for (int i = 0; i < 4; i++) {
            int id = tid + i * 256;
            int r = id >> 4, c8 = (id & 15) * 8;
            size_t g = ((size_t)(kt0 + r) * NKV + kvh) * HD + c8;
            cp_async16(smem_u32(bKh + r * PDD + c8), Kh + g);
            cp_async16(smem_u32(bKl + r * PDD + c8), Kl + g);
            cp_async16(smem_u32(bVh + r * PDD + c8), Vh + g);
            cp_async16(smem_u32(bVl + r * PDD + c8), Vl + g);
        }
        asm volatile("cp.async.commit_group;\n");
    };

    load_kv(t0, 0);

    for (int kt = t0; kt <= t1; kt++) {
        const int buf = (kt - t0) & 1;
        const int kt0 = kt << 6;
        if (kt + 1 <= t1) {
            load_kv(kt + 1, buf ^ 1);
            asm volatile("cp.async.wait_group 1;\n");
        } else {
            asm volatile("cp.async.wait_group 0;\n");
        }
        __syncthreads();

        __nv_bfloat16* base = sKV + buf * 4 * 64 * PDD;
        __nv_bfloat16* bKh = base;
        __nv_bfloat16* bKl = base + 64 * PDD;
        __nv_bfloat16* bVh = base + 2 * 64 * PDD;
        __nv_bfloat16* bVl = base + 3 * 64 * PDD;

        // ---- S = Qh*Kh^T + Ql*Kh^T + Qh*Kl^T ----
        float S[8][4];
#pragma unroll
        for (int nt = 0; nt < 8; nt++)
#pragma unroll
            for (int r = 0; r < 4; r++) S[nt][r] = 0.f;

#pragma unroll
        for (int pass = 0; pass < 3; pass++) {
            const __nv_bfloat16* Asrc = (pass == 1) ? sQl : sQh;
            const __nv_bfloat16* Bsrc = (pass == 2) ? bKl : bKh;
#pragma unroll
            for (int ks = 0; ks < 8; ks++) {
                uint32_t a[4];
                ldsm4(a, smem_u32(Asrc + (warp_row + (lane & 15)) * PDD
                                        + ks * 16 + (lane >> 4) * 8));
#pragma unroll
                for (int n2 = 0; n2 < 4; n2++) {
                    int row = n2 * 16 + ((lane >> 4) & 1) * 8 + (lane & 7);
                    int col = ks * 16 + ((lane >> 3) & 1) * 8;
                    uint32_t b4[4];
                    ldsm4(b4, smem_u32(Bsrc + row * PDD + col));
                    mma16816(S[n2 * 2],     a, b4);
                    mma16816(S[n2 * 2 + 1], a, b4 + 2);
                }
            }
        }

        // ---- mask (edge tiles only) ----
        bool edge = (kt0 + 63 > q0) || (kt0 < q0 + 63 - (WINDOW - 1));
        if (edge) {
#pragma unroll
            for (int nt = 0; nt < 8; nt++) {
                int jc = kt0 + nt * 8 + (lane & 3) * 2;
#pragma unroll
                for (int e = 0; e < 4; e++) {
                    int j = jc + (e & 1);
                    int s = (e < 2) ? s_row0 : s_row1;
                    if (!((j <= s) && (s - j < WINDOW))) S[nt][e] = -1e30f;
                }
            }
        }

        // ---- online softmax ----
        float mx0 = -1e30f, mx1 = -1e30f;
#pragma unroll
        for (int nt = 0; nt < 8; nt++) {
            mx0 = fmaxf(mx0, fmaxf(S[nt][0], S[nt][1]));
            mx1 = fmaxf(mx1, fmaxf(S[nt][2], S[nt][3]));
        }
#pragma unroll
        for (int off = 1; off <= 2; off <<= 1) {
            mx0 = fmaxf(mx0, __shfl_xor_sync(0xffffffffu, mx0, off));
            mx1 = fmaxf(mx1, __shfl_xor_sync(0xffffffffu, mx1, off));
        }
        float mn0 = fmaxf(m0, mx0), mn1 = fmaxf(m1, mx1);
        float al0 = __expf(m0 - mn0), al1 = __expf(m1 - mn1);
        m0 = mn0; m1 = mn1;

        float sum0 = 0.f, sum1 = 0.f;
        uint32_t phi[4][4], plo[4][4];
#pragma unroll
        for (int j2 = 0; j2 < 4; j2++) {
            float p00 = __expf(S[2 * j2][0] - mn0);
            float p01 = __expf(S[2 * j2][1] - mn0);
            float p02 = __expf(S[2 * j2][2] - mn1);
            float p03 = __expf(S[2 * j2][3] - mn1);
            float p10 = __expf(S[2 * j2 + 1][0] - mn0);
            float p11 = __expf(S[2 * j2 + 1][1] - mn0);
            float p12 = __expf(S[2 * j2 + 1][2] - mn1);
            float p13 = __expf(S[2 * j2 + 1][3] - mn1);
            sum0 += p00 + p01 + p10 + p11;
            sum1 += p02 + p03 + p12 + p13;
            split_pack(p00, p01, phi[j2][0], plo[j2][0]);
            split_pack(p02, p03, phi[j2][1], plo[j2][1]);
            split_pack(p10, p11, phi[j2][2], plo[j2][2]);
            split_pack(p12, p13, phi[j2][3], plo[j2][3]);
        }
#pragma unroll
        for (int off = 1; off <= 2; off <<= 1) {
            sum0 += __shfl_xor_sync(0xffffffffu, sum0, off);
            sum1 += __shfl_xor_sync(0xffffffffu, sum1, off);
        }
        l0 = l0 * al0 + sum0;
        l1 = l1 * al1 + sum1;

#pragma unroll
        for (int i = 0; i < 16; i++) {
            o_acc[i][0] *= al0; o_acc[i][1] *= al0;
            o_acc[i][2] *= al1; o_acc[i][3] *= al1;
        }

        // ---- O += Ph*Vh + Pl*Vh + Ph*Vl ----
#pragma unroll
        for (int j2 = 0; j2 < 4; j2++) {
            int row = j2 * 16 + ((lane >> 3) & 1) * 8 + (lane & 7);
#pragma unroll
            for (int d2 = 0; d2 < 8; d2++) {
                int col = d2 * 16 + ((lane >> 4) & 1) * 8;
                uint32_t bh[4], bl[4];
                ldsm4t(bh, smem_u32(bVh + row * PDD + col));
                mma16816(o_acc[d2 * 2],     phi[j2], bh);
                mma16816(o_acc[d2 * 2 + 1], phi[j2], bh + 2);
                mma16816(o_acc[d2 * 2],     plo[j2], bh);
                mma16816(o_acc[d2 * 2 + 1], plo[j2], bh + 2);
                ldsm4t(bl, smem_u32(bVl + row * PDD + col));
                mma16816(o_acc[d2 * 2],     phi[j2], bl);
                mma16816(o_acc[d2 * 2 + 1], phi[j2], bl + 2);
            }
        }
        __syncthreads();
    }

    // ---- write O ----
    float inv0 = 1.0f / l0, inv1 = 1.0f / l1;
#pragma unroll
    for (int d2 = 0; d2 < 16; d2++) {
        int d = d2 * 8 + (lane & 3) * 2;
        *(float2*)&O[((size_t)s_row0 * NH + h_out) * HD + d] =
            make_float2(o_acc[d2][0] * inv0, o_acc[d2][1] * inv0);
        *(float2*)&O[((size_t)s_row1 * NH + h_out) * HD + d] =
            make_float2(o_acc[d2][2] * inv1, o_acc[d2][3] * inv1);
    }
}

// ---------------------------------------------------------------------------
// Launch
// ---------------------------------------------------------------------------
extern "C" void kernel_launch(void* const* d_in, const int* in_sizes, int n_in,
                              void* d_out, int out_size)
{
    const float* x    = (const float*)d_in[0];
    const float* wq   = (const float*)d_in[1];
    const float* wk   = (const float*)d_in[2];
    const float* wv   = (const float*)d_in[3];
    const float* wo   = (const float*)d_in[4];
    const float* cosb = (const float*)d_in[5];
    const float* sinb = (const float*)d_in[6];
    float* out = (float*)d_out;

    float *q, *k, *v, *o;
    __nv_bfloat16 *xs, *os, *wqs, *wks, *wvs, *wos;
    __nv_bfloat16 *qh, *ql, *kh, *kl, *vh, *vl;
    cudaGetSymbolAddress((void**)&q, g_q);
    cudaGetSymbolAddress((void**)&k, g_k);
    cudaGetSymbolAddress((void**)&v, g_v);
    cudaGetSymbolAddress((void**)&o, g_o);
    cudaGetSymbolAddress((void**)&xs, g_xs);
    cudaGetSymbolAddress((void**)&os, g_os);
    cudaGetSymbolAddress((void**)&wqs, g_wqs);
    cudaGetSymbolAddress((void**)&wks, g_wks);
    cudaGetSymbolAddress((void**)&wvs, g_wvs);
    cudaGetSymbolAddress((void**)&wos, g_wos);
    cudaGetSymbolAddress((void**)&qh, g_qh);
    cudaGetSymbolAddress((void**)&ql, g_ql);
    cudaGetSymbolAddress((void**)&kh, g_kh);
    cudaGetSymbolAddress((void**)&kl, g_kl);
    cudaGetSymbolAddress((void**)&vh, g_vh);
    cudaGetSymbolAddress((void**)&vl, g_vl);

    cudaFuncSetAttribute(attn_mma_kernel,
                         cudaFuncAttributeMaxDynamicSharedMemorySize, ATT_SMEM);

    const int T = 256;
    convert_split_kernel<<<(SEQ * DIM + T - 1) / T, T>>>(x, xs, SEQ, DIM, 1);
    convert_split_kernel<<<(QDIM * DIM + T - 1) / T, T>>>(wq, wqs, QDIM, DIM, 0);
    convert_split_kernel<<<(KVDIM * DIM + T - 1) / T, T>>>(wk, wks, KVDIM, DIM, 0);
    convert_split_kernel<<<(KVDIM * DIM + T - 1) / T, T>>>(wv, wvs, KVDIM, DIM, 0);
    convert_split_kernel<<<(DIM * QDIM + T - 1) / T, T>>>(wo, wos, DIM, QDIM, 0);

    {
        dim3 gq(QDIM / BN, SEQ / BM);
        gemm_bf16_nt<<<gq, 256>>>(xs, wqs, q, SEQ, QDIM, K3);
        dim3 gkv(KVDIM / BN, SEQ / BM);
        gemm_bf16_nt<<<gkv, 256>>>(xs, wks, k, SEQ, KVDIM, K3);
        gemm_bf16_nt<<<gkv, 256>>>(xs, wvs, v, SEQ, KVDIM, K3);
    }

    rope_kernel<<<(SEQ * NH * (HD / 2) + T - 1) / T, T>>>(q, cosb, sinb, NH);
    rope_kernel<<<(SEQ * NKV * (HD / 2) + T - 1) / T, T>>>(k, cosb, sinb, NKV);

    // split q/k/v for attention (scale folded into q)
    const float scale = 0.08838834764831845f;
    split2_kernel<<<(SEQ * QDIM + T - 1) / T, T>>>(q, qh, ql, SEQ * QDIM, scale);
    split2_kernel<<<(SEQ * KVDIM + T - 1) / T, T>>>(k, kh, kl, SEQ * KVDIM, 1.0f);
    split2_kernel<<<(SEQ * KVDIM + T - 1) / T, T>>>(v, vh, vl, SEQ * KVDIM, 1.0f);

    // flash attention
    {
        dim3 ga(SEQ / 64, NKV * 2);
        attn_mma_kernel<<<ga, 256, ATT_SMEM>>>(qh, ql, kh, kl, vh, vl, o);
    }

    convert_split_kernel<<<(SEQ * QDIM + T - 1) / T, T>>>(o, os, SEQ, QDIM, 1);
    {
        dim3 go(DIM / BN, SEQ / BM);
        gemm_bf16_nt<<<go, 256>>>(os, wos, out, SEQ, DIM, K3);
    }
}

// round 5
// speedup vs baseline: 9.8322x; 1.6127x over previous
#include <cuda_runtime.h>
#include <cuda_fp16.h>
#include <math.h>
#include <stdint.h>

#define SEQ     2048
#define DIM     4096
#define NH      32
#define NKV     8
#define HD      128
#define WINDOW  1024
#define QDIM    (NH * HD)            // 4096
#define KVDIM   (NKV * HD)           // 1024
#define QKVDIM  (QDIM + 2 * KVDIM)   // 6144
#define K2      (2 * DIM)            // 8192 (2-term split concat)

// ---------------------------------------------------------------------------
// Scratch (__device__ globals; allocation-free)
// ---------------------------------------------------------------------------
__device__ __align__(256) float g_qkv[SEQ * QKVDIM];
__device__ __align__(256) float g_o[SEQ * QDIM];

__device__ __align__(256) __half g_xs   [SEQ * K2];      // x split [hi|lo]
__device__ __align__(256) __half g_os   [SEQ * K2];      // o split [hi|lo]
__device__ __align__(256) __half g_wqkvs[QKVDIM * K2];   // weights [hi|hi]
__device__ __align__(256) __half g_wos  [DIM * K2];

// attention operands (post-rope)
__device__ __align__(256) __half g_qh[SEQ * QDIM], g_ql[SEQ * QDIM];
__device__ __align__(256) __half g_kh[SEQ * KVDIM];
__device__ __align__(256) __half g_vh[SEQ * KVDIM];

// ---------------------------------------------------------------------------
// helpers
// ---------------------------------------------------------------------------
__device__ __forceinline__ uint32_t smem_u32(const void* p) {
    return (uint32_t)__cvta_generic_to_shared(p);
}
__device__ __forceinline__ void cp_async16(uint32_t dst, const void* src) {
    asm volatile("cp.async.cg.shared.global [%0], [%1], 16;\n" :: "r"(dst), "l"(src));
}
__device__ __forceinline__ void mma16816(float* c, const uint32_t* a, const uint32_t* b) {
    asm volatile(
        "mma.sync.aligned.m16n8k16.row.col.f32.f16.f16.f32 "
        "{%0,%1,%2,%3}, {%4,%5,%6,%7}, {%8,%9}, {%0,%1,%2,%3};\n"
        : "+f"(c[0]), "+f"(c[1]), "+f"(c[2]), "+f"(c[3])
        : "r"(a[0]), "r"(a[1]), "r"(a[2]), "r"(a[3]), "r"(b[0]), "r"(b[1]));
}
__device__ __forceinline__ void ldsm4(uint32_t* r, uint32_t addr) {
    asm volatile("ldmatrix.sync.aligned.m8n8.x4.shared.b16 {%0,%1,%2,%3}, [%4];\n"
        : "=r"(r[0]), "=r"(r[1]), "=r"(r[2]), "=r"(r[3]) : "r"(addr));
}
__device__ __forceinline__ void ldsm4t(uint32_t* r, uint32_t addr) {
    asm volatile("ldmatrix.sync.aligned.m8n8.x4.trans.shared.b16 {%0,%1,%2,%3}, [%4];\n"
        : "=r"(r[0]), "=r"(r[1]), "=r"(r[2]), "=r"(r[3]) : "r"(addr));
}
__device__ __forceinline__ void split_pack(float p0, float p1, uint32_t& hi, uint32_t& lo) {
    __half h0 = __float2half_rn(p0), h1 = __float2half_rn(p1);
    hi = ((uint32_t)*(uint16_t*)&h1 << 16) | (uint32_t)*(uint16_t*)&h0;
    __half l0 = __float2half_rn(p0 - __half2float(h0));
    __half l1 = __float2half_rn(p1 - __half2float(h1));
    lo = ((uint32_t)*(uint16_t*)&l1 << 16) | (uint32_t)*(uint16_t*)&l0;
}

// ---------------------------------------------------------------------------
// fp32 -> fp16 2-term split for GEMM K-concat layout
// A-side per row: [hi | lo], B-side per row: [hi | hi]
// ---------------------------------------------------------------------------
__global__ void convert_split4(const float* __restrict__ src,
                               __half* __restrict__ dst,
                               int rows, int K, int a_side)
{
    int idx = blockIdx.x * blockDim.x + threadIdx.x;
    int K4 = K >> 2;
    if (idx >= rows * K4) return;
    int r = idx / K4, c4 = idx - r * K4;
    float4 a = ((const float4*)src)[idx];
    float av[4] = {a.x, a.y, a.z, a.w};
    uint32_t h[4], l[4];
#pragma unroll
    for (int i = 0; i < 4; i++) {
        __half hb = __float2half_rn(av[i]);
        __half lb = __float2half_rn(av[i] - __half2float(hb));
        h[i] = *(uint16_t*)&hb; l[i] = *(uint16_t*)&lb;
    }
    uint2 hv = make_uint2(h[0] | (h[1] << 16), h[2] | (h[3] << 16));
    uint2 lv = make_uint2(l[0] | (l[1] << 16), l[2] | (l[3] << 16));
    __half* d = dst + (size_t)r * (2 * K) + c4 * 4;
    *(uint2*)(d)     = hv;
    *(uint2*)(d + K) = a_side ? lv : hv;
}

// strided fp32 -> (hi, lo) fp16, with scale
__global__ void split2s4(const float* __restrict__ src, int rstride, int coff,
                         __half* __restrict__ hi, __half* __restrict__ lo,
                         int rows, int cols, float scale)
{
    int idx = blockIdx.x * blockDim.x + threadIdx.x;
    int C4 = cols >> 2;
    if (idx >= rows * C4) return;
    int r = idx / C4, c4 = idx - r * C4;
    float4 a = *(const float4*)(src + (size_t)r * rstride + coff + c4 * 4);
    float av[4] = {a.x * scale, a.y * scale, a.z * scale, a.w * scale};
    uint32_t h[4], l[4];
#pragma unroll
    for (int i = 0; i < 4; i++) {
        __half hb = __float2half_rn(av[i]);
        __half lb = __float2half_rn(av[i] - __half2float(hb));
        h[i] = *(uint16_t*)&hb; l[i] = *(uint16_t*)&lb;
    }
    *(uint2*)(hi + (size_t)r * cols + c4 * 4) =
        make_uint2(h[0] | (h[1] << 16), h[2] | (h[3] << 16));
    *(uint2*)(lo + (size_t)r * cols + c4 * 4) =
        make_uint2(l[0] | (l[1] << 16), l[2] | (l[3] << 16));
}

// strided fp32 -> fp16 (hi only)
__global__ void cvt1s4(const float* __restrict__ src, int rstride, int coff,
                       __half* __restrict__ hi, int rows, int cols)
{
    int idx = blockIdx.x * blockDim.x + threadIdx.x;
    int C4 = cols >> 2;
    if (idx >= rows * C4) return;
    int r = idx / C4, c4 = idx - r * C4;
    float4 a = *(const float4*)(src + (size_t)r * rstride + coff + c4 * 4);
    __half h0 = __float2half_rn(a.x), h1 = __float2half_rn(a.y);
    __half h2 = __float2half_rn(a.z), h3 = __float2half_rn(a.w);
    *(uint2*)(hi + (size_t)r * cols + c4 * 4) = make_uint2(
        (uint32_t)*(uint16_t*)&h0 | ((uint32_t)*(uint16_t*)&h1 << 16),
        (uint32_t)*(uint16_t*)&h2 | ((uint32_t)*(uint16_t*)&h3 << 16));
}

// ---------------------------------------------------------------------------
// RoPE on a strided buffer
// ---------------------------------------------------------------------------
__global__ void rope_s(float* __restrict__ t, const float* __restrict__ cosb,
                       const float* __restrict__ sinb, int H, int rstride, int coff)
{
    int idx = blockIdx.x * blockDim.x + threadIdx.x;
    int total = SEQ * H * (HD / 2);
    if (idx >= total) return;
    int p = idx % (HD / 2);
    int h = (idx / (HD / 2)) % H;
    int s = idx / ((HD / 2) * H);
    float c  = cosb[s * (HD / 2) + p];
    float sn = sinb[s * (HD / 2) + p];
    float* base = t + (size_t)s * rstride + coff + h * HD + 2 * p;
    float t0 = base[0], t1 = base[1];
    base[0] = t0 * c - t1 * sn;
    base[1] = t0 * sn + t1 * c;
}

// ---------------------------------------------------------------------------
// fp16 NT GEMM (mma.sync): C[M,N] fp32 = A[M,K]*B[N,K]^T
// 128x128x32 tiles, 8 warps (2x4), warp tile 64x32, double-buffered cp.async
// ---------------------------------------------------------------------------
#define BM 128
#define BN 128
#define BK 32
#define KP 40

__global__ __launch_bounds__(256, 2) void gemm_fp16_nt(
    const __half* __restrict__ A, const __half* __restrict__ B,
    float* __restrict__ C, int M, int N, int K)
{
    __shared__ __half As[2][BM][KP];
    __shared__ __half Bs[2][BN][KP];

    const int tid  = threadIdx.x;
    const int lane = tid & 31;
    const int w    = tid >> 5;
    const int bm   = blockIdx.y * BM;
    const int bn   = blockIdx.x * BN;
    const int warp_m = (w & 1) * 64;
    const int warp_n = (w >> 1) * 32;

    float acc[4][4][4];
#pragma unroll
    for (int i = 0; i < 4; i++)
#pragma unroll
        for (int j = 0; j < 4; j++)
#pragma unroll
            for (int r = 0; r < 4; r++) acc[i][j][r] = 0.0f;

    const int KB = K / BK;

    auto load_stage = [&](int kb, int buf) {
        int k0 = kb * BK;
#pragma unroll
        for (int i = 0; i < 2; i++) {
            int id  = tid + i * 256;
            int row = id >> 2;
            int c8  = (id & 3) * 8;
            cp_async16(smem_u32(&As[buf][row][c8]),
                       A + (size_t)(bm + row) * K + k0 + c8);
            cp_async16(smem_u32(&Bs[buf][row][c8]),
                       B + (size_t)(bn + row) * K + k0 + c8);
        }
        asm volatile("cp.async.commit_group;\n");
    };

    load_stage(0, 0);

    for (int kb = 0; kb < KB; kb++) {
        int buf = kb & 1;
        if (kb + 1 < KB) {
            load_stage(kb + 1, buf ^ 1);
            asm volatile("cp.async.wait_group 1;\n");
        } else {
            asm volatile("cp.async.wait_group 0;\n");
        }
        __syncthreads();

#pragma unroll
        for (int ks = 0; ks < 2; ks++) {
            uint32_t a_frag[4][4];
#pragma unroll
            for (int mt = 0; mt < 4; mt++) {
                uint32_t addr = smem_u32(
                    &As[buf][warp_m + mt * 16 + (lane & 15)][ks * 16 + (lane >> 4) * 8]);
                ldsm4(a_frag[mt], addr);
            }
            uint32_t b_frag[4][2];
#pragma unroll
            for (int half = 0; half < 2; half++) {
                int nt0 = half * 2;
                int row = warp_n + nt0 * 8 + ((lane >> 4) & 1) * 8 + (lane & 7);
                int col = ks * 16 + ((lane >> 3) & 1) * 8;
                uint32_t r4[4];
                ldsm4(r4, smem_u32(&Bs[buf][row][col]));
                b_frag[nt0][0] = r4[0]; b_frag[nt0][1] = r4[1];
                b_frag[nt0 + 1][0] = r4[2]; b_frag[nt0 + 1][1] = r4[3];
            }
#pragma unroll
            for (int mt = 0; mt < 4; mt++)
#pragma unroll
                for (int nt = 0; nt < 4; nt++)
                    mma16816(acc[mt][nt], a_frag[mt], b_frag[nt]);
        }
        __syncthreads();
    }

    const int g   = lane >> 2;
    const int tig = lane & 3;
#pragma unroll
    for (int mt = 0; mt < 4; mt++) {
#pragma unroll
        for (int nt = 0; nt < 4; nt++) {
            float* c0 = C + (size_t)(bm + warp_m + mt * 16 + g) * N
                          + bn + warp_n + nt * 8 + tig * 2;
            float* c1 = c0 + 8 * (size_t)N;
            *(float2*)c0 = make_float2(acc[mt][nt][0], acc[mt][nt][1]);
            *(float2*)c1 = make_float2(acc[mt][nt][2], acc[mt][nt][3]);
        }
    }
}

// ---------------------------------------------------------------------------
// Flash attention, fp16, 2-term precision:
//   S = (Qh + Ql) * Kh^T  (2 passes), O += (Ph + Pl) * Vh
// Block: 64 query positions x 2 heads sharing a kv head -> M=128 rows.
// ---------------------------------------------------------------------------
#define PDD 136
#define ATT_SMEM ((2 * 128 * PDD + 2 * 2 * 64 * PDD) * 2)   // 139264 bytes

__global__ __launch_bounds__(256, 1) void attn_mma_kernel(
    const __half* __restrict__ Qh, const __half* __restrict__ Ql,
    const __half* __restrict__ Kh, const __half* __restrict__ Vh,
    float* __restrict__ O)
{
    extern __shared__ __half sm[];
    __half* sQh = sm;
    __half* sQl = sQh + 128 * PDD;
    __half* sKV = sQl + 128 * PDD;   // 2 bufs x (Kh 64*PDD + Vh 64*PDD)

    const int tid  = threadIdx.x;
    const int lane = tid & 31;
    const int w    = tid >> 5;
    const int q0   = blockIdx.x * 64;
    const int kvh  = blockIdx.y >> 1;
    const int h0   = kvh * 4 + (blockIdx.y & 1) * 2;

    const int warp_row = w * 16;
    const int s_row0 = q0 + (warp_row & 63) + (lane >> 2);
    const int s_row1 = s_row0 + 8;
    const int h_out  = h0 + (warp_row >> 6);

#pragma unroll
    for (int i = 0; i < 8; i++) {
        int id = tid + i * 256;
        int r = id >> 4, c8 = (id & 15) * 8;
        int s = q0 + (r & 63), h = h0 + (r >> 6);
        size_t g = ((size_t)s * NH + h) * HD + c8;
        cp_async16(smem_u32(sQh + r * PDD + c8), Qh + g);
        cp_async16(smem_u32(sQl + r * PDD + c8), Ql + g);
    }
    asm volatile("cp.async.commit_group;\n");

    float m0 = -1e30f, m1 = -1e30f, l0 = 0.f, l1 = 0.f;
    float o_acc[16][4];
#pragma unroll
    for (int i = 0; i < 16; i++)
#pragma unroll
        for (int r = 0; r < 4; r++) o_acc[i][r] = 0.f;

    int jlo = q0 - (WINDOW - 1); if (jlo < 0) jlo = 0;
    const int t0 = jlo >> 6, t1 = (q0 + 63) >> 6;

    auto load_kv = [&](int kt, int buf) {
        __half* b = sKV + buf * 2 * 64 * PDD;
        int kt0 = kt << 6;
#pragma unroll
        for (int i = 0; i < 4; i++) {
            int id = tid + i * 256;
            int r = id >> 4, c8 = (id & 15) * 8;
            size_t g = ((size_t)(kt0 + r) * NKV + kvh) * HD + c8;
            cp_async16(smem_u32(b + r * PDD + c8), Kh + g);
            cp_async16(smem_u32(b + 64 * PDD + r * PDD + c8), Vh + g);
        }
        asm volatile("cp.async.commit_group;\n");
    };

    load_kv(t0, 0);

    for (int kt = t0; kt <= t1; kt++) {
        const int buf = (kt - t0) & 1;
        const int kt0 = kt << 6;
        if (kt + 1 <= t1) {
            load_kv(kt + 1, buf ^ 1);
            asm volatile("cp.async.wait_group 1;\n");
        } else {
            asm volatile("cp.async.wait_group 0;\n");
        }
        __syncthreads();

        __half* bKh = sKV + buf * 2 * 64 * PDD;
        __half* bVh = bKh + 64 * PDD;

        // ---- S = Qh*Kh^T + Ql*Kh^T ----
        float S[8][4];
#pragma unroll
        for (int nt = 0; nt < 8; nt++)
#pragma unroll
            for (int r = 0; r < 4; r++) S[nt][r] = 0.f;

#pragma unroll
        for (int pass = 0; pass < 2; pass++) {
            const __half* Asrc = pass ? sQl : sQh;
#pragma unroll
            for (int ks = 0; ks < 8; ks++) {
                uint32_t a[4];
                ldsm4(a, smem_u32(Asrc + (warp_row + (lane & 15)) * PDD
                                        + ks * 16 + (lane >> 4) * 8));
#pragma unroll
                for (int n2 = 0; n2 < 4; n2++) {
                    int row = n2 * 16 + ((lane >> 4) & 1) * 8 + (lane & 7);
                    int col = ks * 16 + ((lane >> 3) & 1) * 8;
                    uint32_t b4[4];
                    ldsm4(b4, smem_u32(bKh + row * PDD + col));
                    mma16816(S[n2 * 2],     a, b4);
                    mma16816(S[n2 * 2 + 1], a, b4 + 2);
                }
            }
        }

        // ---- mask (edge tiles only) ----
        bool edge = (kt0 + 63 > q0) || (kt0 < q0 + 63 - (WINDOW - 1));
        if (edge) {
#pragma unroll
            for (int nt = 0; nt < 8; nt++) {
                int jc = kt0 + nt * 8 + (lane & 3) * 2;
#pragma unroll
                for (int e = 0; e < 4; e++) {
                    int j = jc + (e & 1);
                    int s = (e < 2) ? s_row0 : s_row1;
                    if (!((j <= s) && (s - j < WINDOW))) S[nt][e] = -1e30f;
                }
            }
        }

        // ---- online softmax ----
        float mx0 = -1e30f, mx1 = -1e30f;
#pragma unroll
        for (int nt = 0; nt < 8; nt++) {
            mx0 = fmaxf(mx0, fmaxf(S[nt][0], S[nt][1]));
            mx1 = fmaxf(mx1, fmaxf(S[nt][2], S[nt][3]));
        }
#pragma unroll
        for (int off = 1; off <= 2; off <<= 1) {
            mx0 = fmaxf(mx0, __shfl_xor_sync(0xffffffffu, mx0, off));
            mx1 = fmaxf(mx1, __shfl_xor_sync(0xffffffffu, mx1, off));
        }
        float mn0 = fmaxf(m0, mx0), mn1 = fmaxf(m1, mx1);
        float al0 = __expf(m0 - mn0), al1 = __expf(m1 - mn1);
        m0 = mn0; m1 = mn1;

        float sum0 = 0.f, sum1 = 0.f;
        uint32_t phi[4][4], plo[4][4];
#pragma unroll
        for (int j2 = 0; j2 < 4; j2++) {
            float p00 = __expf(S[2 * j2][0] - mn0);
            float p01 = __expf(S[2 * j2][1] - mn0);
            float p02 = __expf(S[2 * j2][2] - mn1);
            float p03 = __expf(S[2 * j2][3] - mn1);
            float p10 = __expf(S[2 * j2 + 1][0] - mn0);
            float p11 = __expf(S[2 * j2 + 1][1] - mn0);
            float p12 = __expf(S[2 * j2 + 1][2] - mn1);
            float p13 = __expf(S[2 * j2 + 1][3] - mn1);
            sum0 += p00 + p01 + p10 + p11;
            sum1 += p02 + p03 + p12 + p13;
            split_pack(p00, p01, phi[j2][0], plo[j2][0]);
            split_pack(p02, p03, phi[j2][1], plo[j2][1]);
            split_pack(p10, p11, phi[j2][2], plo[j2][2]);
            split_pack(p12, p13, phi[j2][3], plo[j2][3]);
        }
#pragma unroll
        for (int off = 1; off <= 2; off <<= 1) {
            sum0 += __shfl_xor_sync(0xffffffffu, sum0, off);
            sum1 += __shfl_xor_sync(0xffffffffu, sum1, off);
        }
        l0 = l0 * al0 + sum0;
        l1 = l1 * al1 + sum1;

#pragma unroll
        for (int i = 0; i < 16; i++) {
            o_acc[i][0] *= al0; o_acc[i][1] *= al0;
            o_acc[i][2] *= al1; o_acc[i][3] *= al1;
        }

        // ---- O += (Ph + Pl) * Vh ----
#pragma unroll
        for (int j2 = 0; j2 < 4; j2++) {
            int row = j2 * 16 + ((lane >> 3) & 1) * 8 + (lane & 7);
#pragma unroll
            for (int d2 = 0; d2 < 8; d2++) {
                int col = d2 * 16 + ((lane >> 4) & 1) * 8;
                uint32_t bh[4];
                ldsm4t(bh, smem_u32(bVh + row * PDD + col));
                mma16816(o_acc[d2 * 2],     phi[j2], bh);
                mma16816(o_acc[d2 * 2 + 1], phi[j2], bh + 2);
                mma16816(o_acc[d2 * 2],     plo[j2], bh);
                mma16816(o_acc[d2 * 2 + 1], plo[j2], bh + 2);
            }
        }
        __syncthreads();
    }

    float inv0 = 1.0f / l0, inv1 = 1.0f / l1;
#pragma unroll
    for (int d2 = 0; d2 < 16; d2++) {
        int d = d2 * 8 + (lane & 3) * 2;
        *(float2*)&O[((size_t)s_row0 * NH + h_out) * HD + d] =
            make_float2(o_acc[d2][0] * inv0, o_acc[d2][1] * inv0);
        *(float2*)&O[((size_t)s_row1 * NH + h_out) * HD + d] =
            make_float2(o_acc[d2][2] * inv1, o_acc[d2][3] * inv1);
    }
}

// ---------------------------------------------------------------------------
// Launch
// ---------------------------------------------------------------------------
extern "C" void kernel_launch(void* const* d_in, const int* in_sizes, int n_in,
                              void* d_out, int out_size)
{
    const float* x    = (const float*)d_in[0];
    const float* wq   = (const float*)d_in[1];
    const float* wk   = (const float*)d_in[2];
    const float* wv   = (const float*)d_in[3];
    const float* wo   = (const float*)d_in[4];
    const float* cosb = (const float*)d_in[5];
    const float* sinb = (const float*)d_in[6];
    float* out = (float*)d_out;

    float *qkv, *o;
    __half *xs, *os, *wqkvs, *wos, *qh, *ql, *kh, *vh;
    cudaGetSymbolAddress((void**)&qkv, g_qkv);
    cudaGetSymbolAddress((void**)&o, g_o);
    cudaGetSymbolAddress((void**)&xs, g_xs);
    cudaGetSymbolAddress((void**)&os, g_os);
    cudaGetSymbolAddress((void**)&wqkvs, g_wqkvs);
    cudaGetSymbolAddress((void**)&wos, g_wos);
    cudaGetSymbolAddress((void**)&qh, g_qh);
    cudaGetSymbolAddress((void**)&ql, g_ql);
    cudaGetSymbolAddress((void**)&kh, g_kh);
    cudaGetSymbolAddress((void**)&vh, g_vh);

    cudaFuncSetAttribute(attn_mma_kernel,
                         cudaFuncAttributeMaxDynamicSharedMemorySize, ATT_SMEM);

    const int T = 256;
    // split conversions ([hi|lo] for activations, [hi|hi] for weights)
    convert_split4<<<(SEQ * DIM / 4 + T - 1) / T, T>>>(x, xs, SEQ, DIM, 1);
    convert_split4<<<(QDIM * DIM / 4 + T - 1) / T, T>>>(wq, wqkvs, QDIM, DIM, 0);
    convert_split4<<<(KVDIM * DIM / 4 + T - 1) / T, T>>>(
        wk, wqkvs + (size_t)QDIM * K2, KVDIM, DIM, 0);
    convert_split4<<<(KVDIM * DIM / 4 + T - 1) / T, T>>>(
        wv, wqkvs + (size_t)(QDIM + KVDIM) * K2, KVDIM, DIM, 0);
    convert_split4<<<(DIM * QDIM / 4 + T - 1) / T, T>>>(wo, wos, DIM, QDIM, 0);

    // fused QKV projection
    {
        dim3 g(QKVDIM / BN, SEQ / BM);
        gemm_fp16_nt<<<g, 256>>>(xs, wqkvs, qkv, SEQ, QKVDIM, K2);
    }

    // RoPE on q and k slices of qkv
    rope_s<<<(SEQ * NH * (HD / 2) + T - 1) / T, T>>>(qkv, cosb, sinb, NH, QKVDIM, 0);
    rope_s<<<(SEQ * NKV * (HD / 2) + T - 1) / T, T>>>(qkv, cosb, sinb, NKV, QKVDIM, QDIM);

    // attention operands: q split hi/lo (scale folded), k/v hi-only
    const float scale = 0.08838834764831845f;
    split2s4<<<(SEQ * QDIM / 4 + T - 1) / T, T>>>(qkv, QKVDIM, 0, qh, ql, SEQ, QDIM, scale);
    cvt1s4<<<(SEQ * KVDIM / 4 + T - 1) / T, T>>>(qkv, QKVDIM, QDIM, kh, SEQ, KVDIM);
    cvt1s4<<<(SEQ * KVDIM / 4 + T - 1) / T, T>>>(qkv, QKVDIM, QDIM + KVDIM, vh, SEQ, KVDIM);

    // flash attention
    {
        dim3 ga(SEQ / 64, NKV * 2);
        attn_mma_kernel<<<ga, 256, ATT_SMEM>>>(qh, ql, kh, vh, o);
    }

    // output projection
    convert_split4<<<(SEQ * QDIM / 4 + T - 1) / T, T>>>(o, os, SEQ, QDIM, 1);
    {
        dim3 g(DIM / BN, SEQ / BM);
        gemm_fp16_nt<<<g, 256>>>(os, wos, out, SEQ, DIM, K2);
    }
}

// round 6
// speedup vs baseline: 10.1704x; 1.0344x over previous
#include <cuda_runtime.h>
#include <cuda_fp16.h>
#include <math.h>
#include <stdint.h>

#define SEQ     2048
#define DIM     4096
#define NH      32
#define NKV     8
#define HD      128
#define WINDOW  1024
#define QDIM    (NH * HD)            // 4096
#define KVDIM   (NKV * HD)           // 1024
#define QKVDIM  (QDIM + 2 * KVDIM)   // 6144
#define K2      (2 * DIM)            // 8192

// ---------------------------------------------------------------------------
// Scratch
// ---------------------------------------------------------------------------
__device__ __align__(256) float g_qkv[SEQ * QKVDIM];

__device__ __align__(256) __half g_xs   [SEQ * K2];      // x split [hi|lo]
__device__ __align__(256) __half g_os   [SEQ * K2];      // attn out split [hi|lo]
__device__ __align__(256) __half g_wqkvs[QKVDIM * K2];   // weights [hi|hi]
__device__ __align__(256) __half g_wos  [DIM * K2];

__device__ __align__(256) __half g_qh[SEQ * QDIM], g_ql[SEQ * QDIM];
__device__ __align__(256) __half g_kh[SEQ * KVDIM];
__device__ __align__(256) __half g_vh[SEQ * KVDIM];

// ---------------------------------------------------------------------------
// helpers
// ---------------------------------------------------------------------------
__device__ __forceinline__ uint32_t smem_u32(const void* p) {
    return (uint32_t)__cvta_generic_to_shared(p);
}
__device__ __forceinline__ void cp_async16(uint32_t dst, const void* src) {
    asm volatile("cp.async.cg.shared.global [%0], [%1], 16;\n" :: "r"(dst), "l"(src));
}
__device__ __forceinline__ void mma16816(float* c, const uint32_t* a, const uint32_t* b) {
    asm volatile(
        "mma.sync.aligned.m16n8k16.row.col.f32.f16.f16.f32 "
        "{%0,%1,%2,%3}, {%4,%5,%6,%7}, {%8,%9}, {%0,%1,%2,%3};\n"
        : "+f"(c[0]), "+f"(c[1]), "+f"(c[2]), "+f"(c[3])
        : "r"(a[0]), "r"(a[1]), "r"(a[2]), "r"(a[3]), "r"(b[0]), "r"(b[1]));
}
__device__ __forceinline__ void ldsm4(uint32_t* r, uint32_t addr) {
    asm volatile("ldmatrix.sync.aligned.m8n8.x4.shared.b16 {%0,%1,%2,%3}, [%4];\n"
        : "=r"(r[0]), "=r"(r[1]), "=r"(r[2]), "=r"(r[3]) : "r"(addr));
}
__device__ __forceinline__ void ldsm4t(uint32_t* r, uint32_t addr) {
    asm volatile("ldmatrix.sync.aligned.m8n8.x4.trans.shared.b16 {%0,%1,%2,%3}, [%4];\n"
        : "=r"(r[0]), "=r"(r[1]), "=r"(r[2]), "=r"(r[3]) : "r"(addr));
}
__device__ __forceinline__ void split_pack(float p0, float p1, uint32_t& hi, uint32_t& lo) {
    __half h0 = __float2half_rn(p0), h1 = __float2half_rn(p1);
    hi = ((uint32_t)*(uint16_t*)&h1 << 16) | (uint32_t)*(uint16_t*)&h0;
    __half l0 = __float2half_rn(p0 - __half2float(h0));
    __half l1 = __float2half_rn(p1 - __half2float(h1));
    lo = ((uint32_t)*(uint16_t*)&l1 << 16) | (uint32_t)*(uint16_t*)&l0;
}

// ---------------------------------------------------------------------------
// fp32 -> fp16 2-term split, K-concat layout (GEMM operands)
// ---------------------------------------------------------------------------
__global__ void convert_split4(const float* __restrict__ src,
                               __half* __restrict__ dst,
                               int rows, int K, int a_side)
{
    int idx = blockIdx.x * blockDim.x + threadIdx.x;
    int K4 = K >> 2;
    if (idx >= rows * K4) return;
    int r = idx / K4, c4 = idx - r * K4;
    float4 a = ((const float4*)src)[idx];
    float av[4] = {a.x, a.y, a.z, a.w};
    uint32_t h[4], l[4];
#pragma unroll
    for (int i = 0; i < 4; i++) {
        __half hb = __float2half_rn(av[i]);
        __half lb = __float2half_rn(av[i] - __half2float(hb));
        h[i] = *(uint16_t*)&hb; l[i] = *(uint16_t*)&lb;
    }
    uint2 hv = make_uint2(h[0] | (h[1] << 16), h[2] | (h[3] << 16));
    uint2 lv = make_uint2(l[0] | (l[1] << 16), l[2] | (l[3] << 16));
    __half* d = dst + (size_t)r * (2 * K) + c4 * 4;
    *(uint2*)(d)     = hv;
    *(uint2*)(d + K) = a_side ? lv : hv;
}

// ---------------------------------------------------------------------------
// Fused rope + scale + hi/lo split for Q (reads qkv, writes qh/ql)
// ---------------------------------------------------------------------------
__global__ void rope_split_q(const float* __restrict__ qkv,
                             const float* __restrict__ cosb,
                             const float* __restrict__ sinb,
                             __half* __restrict__ qh, __half* __restrict__ ql,
                             float scale)
{
    int idx = blockIdx.x * blockDim.x + threadIdx.x;
    if (idx >= SEQ * NH * (HD / 2)) return;
    int p = idx % (HD / 2);
    int h = (idx / (HD / 2)) % NH;
    int s = idx / ((HD / 2) * NH);
    float c  = cosb[s * (HD / 2) + p];
    float sn = sinb[s * (HD / 2) + p];
    const float* base = qkv + (size_t)s * QKVDIM + h * HD + 2 * p;
    float t0 = base[0], t1 = base[1];
    float r0 = (t0 * c - t1 * sn) * scale;
    float r1 = (t0 * sn + t1 * c) * scale;
    uint32_t hi, lo;
    split_pack(r0, r1, hi, lo);
    size_t o = (size_t)s * QDIM + h * HD + 2 * p;
    *(uint32_t*)(qh + o) = hi;
    *(uint32_t*)(ql + o) = lo;
}

// Fused rope + fp16 cvt for K
__global__ void rope_cvt_k(const float* __restrict__ qkv,
                           const float* __restrict__ cosb,
                           const float* __restrict__ sinb,
                           __half* __restrict__ kh)
{
    int idx = blockIdx.x * blockDim.x + threadIdx.x;
    if (idx >= SEQ * NKV * (HD / 2)) return;
    int p = idx % (HD / 2);
    int h = (idx / (HD / 2)) % NKV;
    int s = idx / ((HD / 2) * NKV);
    float c  = cosb[s * (HD / 2) + p];
    float sn = sinb[s * (HD / 2) + p];
    const float* base = qkv + (size_t)s * QKVDIM + QDIM + h * HD + 2 * p;
    float t0 = base[0], t1 = base[1];
    __half h0 = __float2half_rn(t0 * c - t1 * sn);
    __half h1 = __float2half_rn(t0 * sn + t1 * c);
    *(uint32_t*)(kh + (size_t)s * KVDIM + h * HD + 2 * p) =
        (uint32_t)*(uint16_t*)&h0 | ((uint32_t)*(uint16_t*)&h1 << 16);
}

// strided fp32 -> fp16 (V)
__global__ void cvt_v(const float* __restrict__ qkv, __half* __restrict__ vh)
{
    int idx = blockIdx.x * blockDim.x + threadIdx.x;
    int C4 = KVDIM >> 2;
    if (idx >= SEQ * C4) return;
    int r = idx / C4, c4 = idx - r * C4;
    float4 a = *(const float4*)(qkv + (size_t)r * QKVDIM + QDIM + KVDIM + c4 * 4);
    __half h0 = __float2half_rn(a.x), h1 = __float2half_rn(a.y);
    __half h2 = __float2half_rn(a.z), h3 = __float2half_rn(a.w);
    *(uint2*)(vh + (size_t)r * KVDIM + c4 * 4) = make_uint2(
        (uint32_t)*(uint16_t*)&h0 | ((uint32_t)*(uint16_t*)&h1 << 16),
        (uint32_t)*(uint16_t*)&h2 | ((uint32_t)*(uint16_t*)&h3 << 16));
}

// ---------------------------------------------------------------------------
// fp16 NT GEMM, 4-stage cp.async ring, one barrier per K-block.
// 128x128x32 tiles, 8 warps (2x4), warp tile 64x32.
// ---------------------------------------------------------------------------
#define BM 128
#define BN 128
#define BK 32
#define KP 40
#define NST 4
#define STG_H ((BM + BN) * KP)                 // halves per stage
#define GEMM_SMEM (NST * STG_H * 2)            // 81920 bytes

__global__ __launch_bounds__(256, 2) void gemm_fp16_nt(
    const __half* __restrict__ A, const __half* __restrict__ B,
    float* __restrict__ C, int M, int N, int K)
{
    extern __shared__ __half smg[];

    const int tid  = threadIdx.x;
    const int lane = tid & 31;
    const int w    = tid >> 5;
    const int bm   = blockIdx.y * BM;
    const int bn   = blockIdx.x * BN;
    const int warp_m = (w & 1) * 64;
    const int warp_n = (w >> 1) * 32;

    float acc[4][4][4];
#pragma unroll
    for (int i = 0; i < 4; i++)
#pragma unroll
        for (int j = 0; j < 4; j++)
#pragma unroll
            for (int r = 0; r < 4; r++) acc[i][j][r] = 0.0f;

    const int KB = K / BK;

    auto load_stage = [&](int kb) {
        __half* As = smg + (kb & (NST - 1)) * STG_H;
        __half* Bs = As + BM * KP;
        int k0 = kb * BK;
#pragma unroll
        for (int i = 0; i < 2; i++) {
            int id  = tid + i * 256;
            int row = id >> 2;
            int c8  = (id & 3) * 8;
            cp_async16(smem_u32(As + row * KP + c8),
                       A + (size_t)(bm + row) * K + k0 + c8);
            cp_async16(smem_u32(Bs + row * KP + c8),
                       B + (size_t)(bn + row) * K + k0 + c8);
        }
        asm volatile("cp.async.commit_group;\n");
    };

    load_stage(0);
    load_stage(1);
    load_stage(2);

    for (int kb = 0; kb < KB; kb++) {
        asm volatile("cp.async.wait_group 2;\n");   // stage kb landed
        __syncthreads();                            // all threads' stage-kb data visible
        if (kb + 3 < KB) {
            load_stage(kb + 3);                     // reuses buffer of stage kb-1
        } else {
            asm volatile("cp.async.commit_group;\n");
        }

        __half* As = smg + (kb & (NST - 1)) * STG_H;
        __half* Bs = As + BM * KP;

#pragma unroll
        for (int ks = 0; ks < 2; ks++) {
            uint32_t a_frag[4][4];
#pragma unroll
            for (int mt = 0; mt < 4; mt++) {
                uint32_t addr = smem_u32(
                    As + (warp_m + mt * 16 + (lane & 15)) * KP
                       + ks * 16 + (lane >> 4) * 8);
                ldsm4(a_frag[mt], addr);
            }
            uint32_t b_frag[4][2];
#pragma unroll
            for (int half = 0; half < 2; half++) {
                int nt0 = half * 2;
                int row = warp_n + nt0 * 8 + ((lane >> 4) & 1) * 8 + (lane & 7);
                int col = ks * 16 + ((lane >> 3) & 1) * 8;
                uint32_t r4[4];
                ldsm4(r4, smem_u32(Bs + row * KP + col));
                b_frag[nt0][0] = r4[0]; b_frag[nt0][1] = r4[1];
                b_frag[nt0 + 1][0] = r4[2]; b_frag[nt0 + 1][1] = r4[3];
            }
#pragma unroll
            for (int mt = 0; mt < 4; mt++)
#pragma unroll
                for (int nt = 0; nt < 4; nt++)
                    mma16816(acc[mt][nt], a_frag[mt], b_frag[nt]);
        }
    }

    const int g   = lane >> 2;
    const int tig = lane & 3;
#pragma unroll
    for (int mt = 0; mt < 4; mt++) {
#pragma unroll
        for (int nt = 0; nt < 4; nt++) {
            float* c0 = C + (size_t)(bm + warp_m + mt * 16 + g) * N
                          + bn + warp_n + nt * 8 + tig * 2;
            float* c1 = c0 + 8 * (size_t)N;
            *(float2*)c0 = make_float2(acc[mt][nt][0], acc[mt][nt][1]);
            *(float2*)c1 = make_float2(acc[mt][nt][2], acc[mt][nt][3]);
        }
    }
}

// ---------------------------------------------------------------------------
// Flash attention, fp16, 2-term: S = (Qh+Ql)*Kh^T, O += (Ph+Pl)*Vh.
// Writes the [hi|lo] K-concat split output directly (feeds WO GEMM).
// ---------------------------------------------------------------------------
#define PDD 136
#define ATT_SMEM ((2 * 128 * PDD + 2 * 2 * 64 * PDD) * 2)

__global__ __launch_bounds__(256, 1) void attn_mma_kernel(
    const __half* __restrict__ Qh, const __half* __restrict__ Ql,
    const __half* __restrict__ Kh, const __half* __restrict__ Vh,
    __half* __restrict__ OS)
{
    extern __shared__ __half sm[];
    __half* sQh = sm;
    __half* sQl = sQh + 128 * PDD;
    __half* sKV = sQl + 128 * PDD;

    const int tid  = threadIdx.x;
    const int lane = tid & 31;
    const int w    = tid >> 5;
    const int q0   = blockIdx.x * 64;
    const int kvh  = blockIdx.y >> 1;
    const int h0   = kvh * 4 + (blockIdx.y & 1) * 2;

    const int warp_row = w * 16;
    const int s_row0 = q0 + (warp_row & 63) + (lane >> 2);
    const int s_row1 = s_row0 + 8;
    const int h_out  = h0 + (warp_row >> 6);

#pragma unroll
    for (int i = 0; i < 8; i++) {
        int id = tid + i * 256;
        int r = id >> 4, c8 = (id & 15) * 8;
        int s = q0 + (r & 63), h = h0 + (r >> 6);
        size_t g = ((size_t)s * NH + h) * HD + c8;
        cp_async16(smem_u32(sQh + r * PDD + c8), Qh + g);
        cp_async16(smem_u32(sQl + r * PDD + c8), Ql + g);
    }
    asm volatile("cp.async.commit_group;\n");

    float m0 = -1e30f, m1 = -1e30f, l0 = 0.f, l1 = 0.f;
    float o_acc[16][4];
#pragma unroll
    for (int i = 0; i < 16; i++)
#pragma unroll
        for (int r = 0; r < 4; r++) o_acc[i][r] = 0.f;

    int jlo = q0 - (WINDOW - 1); if (jlo < 0) jlo = 0;
    const int t0 = jlo >> 6, t1 = (q0 + 63) >> 6;

    auto load_kv = [&](int kt, int buf) {
        __half* b = sKV + buf * 2 * 64 * PDD;
        int kt0 = kt << 6;
#pragma unroll
        for (int i = 0; i < 4; i++) {
            int id = tid + i * 256;
            int r = id >> 4, c8 = (id & 15) * 8;
            size_t g = ((size_t)(kt0 + r) * NKV + kvh) * HD + c8;
            cp_async16(smem_u32(b + r * PDD + c8), Kh + g);
            cp_async16(smem_u32(b + 64 * PDD + r * PDD + c8), Vh + g);
        }
        asm volatile("cp.async.commit_group;\n");
    };

    load_kv(t0, 0);

    for (int kt = t0; kt <= t1; kt++) {
        const int buf = (kt - t0) & 1;
        const int kt0 = kt << 6;
        if (kt + 1 <= t1) {
            load_kv(kt + 1, buf ^ 1);
            asm volatile("cp.async.wait_group 1;\n");
        } else {
            asm volatile("cp.async.wait_group 0;\n");
        }
        __syncthreads();

        __half* bKh = sKV + buf * 2 * 64 * PDD;
        __half* bVh = bKh + 64 * PDD;

        float S[8][4];
#pragma unroll
        for (int nt = 0; nt < 8; nt++)
#pragma unroll
            for (int r = 0; r < 4; r++) S[nt][r] = 0.f;

#pragma unroll
        for (int pass = 0; pass < 2; pass++) {
            const __half* Asrc = pass ? sQl : sQh;
#pragma unroll
            for (int ks = 0; ks < 8; ks++) {
                uint32_t a[4];
                ldsm4(a, smem_u32(Asrc + (warp_row + (lane & 15)) * PDD
                                        + ks * 16 + (lane >> 4) * 8));
#pragma unroll
                for (int n2 = 0; n2 < 4; n2++) {
                    int row = n2 * 16 + ((lane >> 4) & 1) * 8 + (lane & 7);
                    int col = ks * 16 + ((lane >> 3) & 1) * 8;
                    uint32_t b4[4];
                    ldsm4(b4, smem_u32(bKh + row * PDD + col));
                    mma16816(S[n2 * 2],     a, b4);
                    mma16816(S[n2 * 2 + 1], a, b4 + 2);
                }
            }
        }

        bool edge = (kt0 + 63 > q0) || (kt0 < q0 + 63 - (WINDOW - 1));
        if (edge) {
#pragma unroll
            for (int nt = 0; nt < 8; nt++) {
                int jc = kt0 + nt * 8 + (lane & 3) * 2;
#pragma unroll
                for (int e = 0; e < 4; e++) {
                    int j = jc + (e & 1);
                    int s = (e < 2) ? s_row0 : s_row1;
                    if (!((j <= s) && (s - j < WINDOW))) S[nt][e] = -1e30f;
                }
            }
        }

        float mx0 = -1e30f, mx1 = -1e30f;
#pragma unroll
        for (int nt = 0; nt < 8; nt++) {
            mx0 = fmaxf(mx0, fmaxf(S[nt][0], S[nt][1]));
            mx1 = fmaxf(mx1, fmaxf(S[nt][2], S[nt][3]));
        }
#pragma unroll
        for (int off = 1; off <= 2; off <<= 1) {
            mx0 = fmaxf(mx0, __shfl_xor_sync(0xffffffffu, mx0, off));
            mx1 = fmaxf(mx1, __shfl_xor_sync(0xffffffffu, mx1, off));
        }
        float mn0 = fmaxf(m0, mx0), mn1 = fmaxf(m1, mx1);
        float al0 = __expf(m0 - mn0), al1 = __expf(m1 - mn1);
        m0 = mn0; m1 = mn1;

        float sum0 = 0.f, sum1 = 0.f;
        uint32_t phi[4][4], plo[4][4];
#pragma unroll
        for (int j2 = 0; j2 < 4; j2++) {
            float p00 = __expf(S[2 * j2][0] - mn0);
            float p01 = __expf(S[2 * j2][1] - mn0);
            float p02 = __expf(S[2 * j2][2] - mn1);
            float p03 = __expf(S[2 * j2][3] - mn1);
            float p10 = __expf(S[2 * j2 + 1][0] - mn0);
            float p11 = __expf(S[2 * j2 + 1][1] - mn0);
            float p12 = __expf(S[2 * j2 + 1][2] - mn1);
            float p13 = __expf(S[2 * j2 + 1][3] - mn1);
            sum0 += p00 + p01 + p10 + p11;
            sum1 += p02 + p03 + p12 + p13;
            split_pack(p00, p01, phi[j2][0], plo[j2][0]);
            split_pack(p02, p03, phi[j2][1], plo[j2][1]);
            split_pack(p10, p11, phi[j2][2], plo[j2][2]);
            split_pack(p12, p13, phi[j2][3], plo[j2][3]);
        }
#pragma unroll
        for (int off = 1; off <= 2; off <<= 1) {
            sum0 += __shfl_xor_sync(0xffffffffu, sum0, off);
            sum1 += __shfl_xor_sync(0xffffffffu, sum1, off);
        }
        l0 = l0 * al0 + sum0;
        l1 = l1 * al1 + sum1;

#pragma unroll
        for (int i = 0; i < 16; i++) {
            o_acc[i][0] *= al0; o_acc[i][1] *= al0;
            o_acc[i][2] *= al1; o_acc[i][3] *= al1;
        }

#pragma unroll
        for (int j2 = 0; j2 < 4; j2++) {
            int row = j2 * 16 + ((lane >> 3) & 1) * 8 + (lane & 7);
#pragma unroll
            for (int d2 = 0; d2 < 8; d2++) {
                int col = d2 * 16 + ((lane >> 4) & 1) * 8;
                uint32_t bh[4];
                ldsm4t(bh, smem_u32(bVh + row * PDD + col));
                mma16816(o_acc[d2 * 2],     phi[j2], bh);
                mma16816(o_acc[d2 * 2 + 1], phi[j2], bh + 2);
                mma16816(o_acc[d2 * 2],     plo[j2], bh);
                mma16816(o_acc[d2 * 2 + 1], plo[j2], bh + 2);
            }
        }
        __syncthreads();
    }

    // ---- write [hi|lo] K-concat split output directly ----
    float inv0 = 1.0f / l0, inv1 = 1.0f / l1;
#pragma unroll
    for (int d2 = 0; d2 < 16; d2++) {
        int d = d2 * 8 + (lane & 3) * 2;
        uint32_t hi, lo;
        split_pack(o_acc[d2][0] * inv0, o_acc[d2][1] * inv0, hi, lo);
        size_t b0 = (size_t)s_row0 * K2 + h_out * HD + d;
        *(uint32_t*)(OS + b0)        = hi;
        *(uint32_t*)(OS + b0 + QDIM) = lo;
        split_pack(o_acc[d2][2] * inv1, o_acc[d2][3] * inv1, hi, lo);
        size_t b1 = (size_t)s_row1 * K2 + h_out * HD + d;
        *(uint32_t*)(OS + b1)        = hi;
        *(uint32_t*)(OS + b1 + QDIM) = lo;
    }
}

// ---------------------------------------------------------------------------
// Launch
// ---------------------------------------------------------------------------
extern "C" void kernel_launch(void* const* d_in, const int* in_sizes, int n_in,
                              void* d_out, int out_size)
{
    const float* x    = (const float*)d_in[0];
    const float* wq   = (const float*)d_in[1];
    const float* wk   = (const float*)d_in[2];
    const float* wv   = (const float*)d_in[3];
    const float* wo   = (const float*)d_in[4];
    const float* cosb = (const float*)d_in[5];
    const float* sinb = (const float*)d_in[6];
    float* out = (float*)d_out;

    float *qkv;
    __half *xs, *os, *wqkvs, *wos, *qh, *ql, *kh, *vh;
    cudaGetSymbolAddress((void**)&qkv, g_qkv);
    cudaGetSymbolAddress((void**)&xs, g_xs);
    cudaGetSymbolAddress((void**)&os, g_os);
    cudaGetSymbolAddress((void**)&wqkvs, g_wqkvs);
    cudaGetSymbolAddress((void**)&wos, g_wos);
    cudaGetSymbolAddress((void**)&qh, g_qh);
    cudaGetSymbolAddress((void**)&ql, g_ql);
    cudaGetSymbolAddress((void**)&kh, g_kh);
    cudaGetSymbolAddress((void**)&vh, g_vh);

    cudaFuncSetAttribute(gemm_fp16_nt,
                         cudaFuncAttributeMaxDynamicSharedMemorySize, GEMM_SMEM);
    cudaFuncSetAttribute(attn_mma_kernel,
                         cudaFuncAttributeMaxDynamicSharedMemorySize, ATT_SMEM);

    const int T = 256;
    convert_split4<<<(SEQ * DIM / 4 + T - 1) / T, T>>>(x, xs, SEQ, DIM, 1);
    convert_split4<<<(QDIM * DIM / 4 + T - 1) / T, T>>>(wq, wqkvs, QDIM, DIM, 0);
    convert_split4<<<(KVDIM * DIM / 4 + T - 1) / T, T>>>(
        wk, wqkvs + (size_t)QDIM * K2, KVDIM, DIM, 0);
    convert_split4<<<(KVDIM * DIM / 4 + T - 1) / T, T>>>(
        wv, wqkvs + (size_t)(QDIM + KVDIM) * K2, KVDIM, DIM, 0);
    convert_split4<<<(DIM * QDIM / 4 + T - 1) / T, T>>>(wo, wos, DIM, QDIM, 0);

    // fused QKV projection
    {
        dim3 g(QKVDIM / BN, SEQ / BM);
        gemm_fp16_nt<<<g, 256, GEMM_SMEM>>>(xs, wqkvs, qkv, SEQ, QKVDIM, K2);
    }

    // fused rope + split / cvt
    const float scale = 0.08838834764831845f;
    rope_split_q<<<(SEQ * NH * (HD / 2) + T - 1) / T, T>>>(qkv, cosb, sinb, qh, ql, scale);
    rope_cvt_k<<<(SEQ * NKV * (HD / 2) + T - 1) / T, T>>>(qkv, cosb, sinb, kh);
    cvt_v<<<(SEQ * KVDIM / 4 + T - 1) / T, T>>>(qkv, vh);

    // flash attention (emits [hi|lo] split output)
    {
        dim3 ga(SEQ / 64, NKV * 2);
        attn_mma_kernel<<<ga, 256, ATT_SMEM>>>(qh, ql, kh, vh, os);
    }

    // output projection
    {
        dim3 g(DIM / BN, SEQ / BM);
        gemm_fp16_nt<<<g, 256, GEMM_SMEM>>>(os, wos, out, SEQ, DIM, K2);
    }
}

// round 7
// speedup vs baseline: 10.4473x; 1.0272x over previous
#include <cuda_runtime.h>
#include <cuda_fp16.h>
#include <math.h>
#include <stdint.h>

#define SEQ     2048
#define DIM     4096
#define NH      32
#define NKV     8
#define HD      128
#define WINDOW  1024
#define QDIM    (NH * HD)            // 4096
#define KVDIM   (NKV * HD)           // 1024
#define QKVDIM  (QDIM + 2 * KVDIM)   // 6144
#define K2      (2 * DIM)            // 8192
#define ATT_SCALE 0.08838834764831845f

// ---------------------------------------------------------------------------
// Scratch
// ---------------------------------------------------------------------------
__device__ __align__(256) __half g_xs   [SEQ * K2];      // x split [hi|lo]
__device__ __align__(256) __half g_os   [SEQ * K2];      // attn out split [hi|lo]
__device__ __align__(256) __half g_wqkvs[QKVDIM * K2];   // weights [hi|hi]
__device__ __align__(256) __half g_wos  [DIM * K2];

__device__ __align__(256) __half g_qh[SEQ * QDIM], g_ql[SEQ * QDIM];
__device__ __align__(256) __half g_kh[SEQ * KVDIM];
__device__ __align__(256) __half g_vh[SEQ * KVDIM];

// ---------------------------------------------------------------------------
// helpers
// ---------------------------------------------------------------------------
__device__ __forceinline__ uint32_t smem_u32(const void* p) {
    return (uint32_t)__cvta_generic_to_shared(p);
}
__device__ __forceinline__ void cp_async16(uint32_t dst, const void* src) {
    asm volatile("cp.async.cg.shared.global [%0], [%1], 16;\n" :: "r"(dst), "l"(src));
}
__device__ __forceinline__ void mma16816(float* c, const uint32_t* a, const uint32_t* b) {
    asm volatile(
        "mma.sync.aligned.m16n8k16.row.col.f32.f16.f16.f32 "
        "{%0,%1,%2,%3}, {%4,%5,%6,%7}, {%8,%9}, {%0,%1,%2,%3};\n"
        : "+f"(c[0]), "+f"(c[1]), "+f"(c[2]), "+f"(c[3])
        : "r"(a[0]), "r"(a[1]), "r"(a[2]), "r"(a[3]), "r"(b[0]), "r"(b[1]));
}
__device__ __forceinline__ void ldsm4(uint32_t* r, uint32_t addr) {
    asm volatile("ldmatrix.sync.aligned.m8n8.x4.shared.b16 {%0,%1,%2,%3}, [%4];\n"
        : "=r"(r[0]), "=r"(r[1]), "=r"(r[2]), "=r"(r[3]) : "r"(addr));
}
__device__ __forceinline__ void ldsm4t(uint32_t* r, uint32_t addr) {
    asm volatile("ldmatrix.sync.aligned.m8n8.x4.trans.shared.b16 {%0,%1,%2,%3}, [%4];\n"
        : "=r"(r[0]), "=r"(r[1]), "=r"(r[2]), "=r"(r[3]) : "r"(addr));
}
__device__ __forceinline__ uint32_t pack2h(float p0, float p1) {
    __half h0 = __float2half_rn(p0), h1 = __float2half_rn(p1);
    return ((uint32_t)*(uint16_t*)&h1 << 16) | (uint32_t)*(uint16_t*)&h0;
}
__device__ __forceinline__ void split_pack(float p0, float p1, uint32_t& hi, uint32_t& lo) {
    __half h0 = __float2half_rn(p0), h1 = __float2half_rn(p1);
    hi = ((uint32_t)*(uint16_t*)&h1 << 16) | (uint32_t)*(uint16_t*)&h0;
    __half l0 = __float2half_rn(p0 - __half2float(h0));
    __half l1 = __float2half_rn(p1 - __half2float(h1));
    lo = ((uint32_t)*(uint16_t*)&l1 << 16) | (uint32_t)*(uint16_t*)&l0;
}

// ---------------------------------------------------------------------------
// fp32 -> fp16 2-term split, K-concat layout, 8 elems/thread (16B stores)
// A-side per row: [hi | lo], B-side per row: [hi | hi]
// ---------------------------------------------------------------------------
__global__ void convert_split8(const float* __restrict__ src,
                               __half* __restrict__ dst,
                               int rows, int K, int a_side)
{
    int idx = blockIdx.x * blockDim.x + threadIdx.x;
    int K8 = K >> 3;
    if (idx >= rows * K8) return;
    int r = idx / K8, c8 = (idx - r * K8) * 8;
    float4 a0 = *(const float4*)(src + (size_t)r * K + c8);
    float4 a1 = *(const float4*)(src + (size_t)r * K + c8 + 4);
    float av[8] = {a0.x, a0.y, a0.z, a0.w, a1.x, a1.y, a1.z, a1.w};
    uint32_t hv[4], lv[4];
#pragma unroll
    for (int i = 0; i < 4; i++) {
        __half h0 = __float2half_rn(av[2 * i]);
        __half h1 = __float2half_rn(av[2 * i + 1]);
        hv[i] = ((uint32_t)*(uint16_t*)&h1 << 16) | (uint32_t)*(uint16_t*)&h0;
        __half l0 = __float2half_rn(av[2 * i]     - __half2float(h0));
        __half l1 = __float2half_rn(av[2 * i + 1] - __half2float(h1));
        lv[i] = ((uint32_t)*(uint16_t*)&l1 << 16) | (uint32_t)*(uint16_t*)&l0;
    }
    __half* d = dst + (size_t)r * (2 * K) + c8;
    *(uint4*)(d) = make_uint4(hv[0], hv[1], hv[2], hv[3]);
    *(uint4*)(d + K) = a_side ? make_uint4(lv[0], lv[1], lv[2], lv[3])
                              : make_uint4(hv[0], hv[1], hv[2], hv[3]);
}

// ---------------------------------------------------------------------------
// fp16 NT GEMM, 4-stage cp.async ring. 128x128x32 tiles, 8 warps (2Mx4N),
// warp tile 64x32. EPI=0: plain fp32 C. EPI=1: fused rope/scale/split
// epilogue writing qh/ql/kh/vh (QKV projection).
// ---------------------------------------------------------------------------
#define BM 128
#define BN 128
#define BK 32
#define KP 40
#define NST 4
#define STG_H ((BM + BN) * KP)
#define GEMM_SMEM (NST * STG_H * 2)   // 81920 bytes

template <int EPI>
__global__ __launch_bounds__(256, 2) void gemm_fp16_nt(
    const __half* __restrict__ A, const __half* __restrict__ B,
    float* __restrict__ C,
    __half* __restrict__ Qh, __half* __restrict__ Ql,
    __half* __restrict__ Kh, __half* __restrict__ Vh,
    const float* __restrict__ cosb, const float* __restrict__ sinb,
    int M, int N, int K)
{
    extern __shared__ __half smg[];

    const int tid  = threadIdx.x;
    const int lane = tid & 31;
    const int w    = tid >> 5;
    const int bm   = blockIdx.y * BM;
    const int bn   = blockIdx.x * BN;
    const int warp_m = (w & 1) * 64;
    const int warp_n = (w >> 1) * 32;

    float acc[4][4][4];
#pragma unroll
    for (int i = 0; i < 4; i++)
#pragma unroll
        for (int j = 0; j < 4; j++)
#pragma unroll
            for (int r = 0; r < 4; r++) acc[i][j][r] = 0.0f;

    const int KB = K / BK;

    auto load_stage = [&](int kb) {
        __half* As = smg + (kb & (NST - 1)) * STG_H;
        __half* Bs = As + BM * KP;
        int k0 = kb * BK;
#pragma unroll
        for (int i = 0; i < 2; i++) {
            int id  = tid + i * 256;
            int row = id >> 2;
            int c8  = (id & 3) * 8;
            cp_async16(smem_u32(As + row * KP + c8),
                       A + (size_t)(bm + row) * K + k0 + c8);
            cp_async16(smem_u32(Bs + row * KP + c8),
                       B + (size_t)(bn + row) * K + k0 + c8);
        }
        asm volatile("cp.async.commit_group;\n");
    };

    load_stage(0);
    load_stage(1);
    load_stage(2);

    for (int kb = 0; kb < KB; kb++) {
        asm volatile("cp.async.wait_group 2;\n");
        __syncthreads();
        if (kb + 3 < KB) {
            load_stage(kb + 3);
        } else {
            asm volatile("cp.async.commit_group;\n");
        }

        __half* As = smg + (kb & (NST - 1)) * STG_H;
        __half* Bs = As + BM * KP;

#pragma unroll
        for (int ks = 0; ks < 2; ks++) {
            uint32_t a_frag[4][4];
#pragma unroll
            for (int mt = 0; mt < 4; mt++) {
                uint32_t addr = smem_u32(
                    As + (warp_m + mt * 16 + (lane & 15)) * KP
                       + ks * 16 + (lane >> 4) * 8);
                ldsm4(a_frag[mt], addr);
            }
            uint32_t b_frag[4][2];
#pragma unroll
            for (int half = 0; half < 2; half++) {
                int nt0 = half * 2;
                int row = warp_n + nt0 * 8 + ((lane >> 4) & 1) * 8 + (lane & 7);
                int col = ks * 16 + ((lane >> 3) & 1) * 8;
                uint32_t r4[4];
                ldsm4(r4, smem_u32(Bs + row * KP + col));
                b_frag[nt0][0] = r4[0]; b_frag[nt0][1] = r4[1];
                b_frag[nt0 + 1][0] = r4[2]; b_frag[nt0 + 1][1] = r4[3];
            }
#pragma unroll
            for (int mt = 0; mt < 4; mt++)
#pragma unroll
                for (int nt = 0; nt < 4; nt++)
                    mma16816(acc[mt][nt], a_frag[mt], b_frag[nt]);
        }
    }

    const int g   = lane >> 2;
    const int tig = lane & 3;

    if (EPI == 0) {
#pragma unroll
        for (int mt = 0; mt < 4; mt++) {
#pragma unroll
            for (int nt = 0; nt < 4; nt++) {
                float* c0 = C + (size_t)(bm + warp_m + mt * 16 + g) * N
                              + bn + warp_n + nt * 8 + tig * 2;
                float* c1 = c0 + 8 * (size_t)N;
                *(float2*)c0 = make_float2(acc[mt][nt][0], acc[mt][nt][1]);
                *(float2*)c1 = make_float2(acc[mt][nt][2], acc[mt][nt][3]);
            }
        }
    } else {
        // region is uniform per block (BN=128 divides region boundaries)
        const int region = (bn < QDIM) ? 0 : ((bn < QDIM + KVDIM) ? 1 : 2);
#pragma unroll
        for (int mt = 0; mt < 4; mt++) {
            int row0 = bm + warp_m + mt * 16 + g;
            int row1 = row0 + 8;
#pragma unroll
            for (int nt = 0; nt < 4; nt++) {
                int n0 = bn + warp_n + nt * 8 + tig * 2;
                float a00 = acc[mt][nt][0], a01 = acc[mt][nt][1];
                float a10 = acc[mt][nt][2], a11 = acc[mt][nt][3];
                if (region == 2) {
                    int col = n0 - (QDIM + KVDIM);
                    *(uint32_t*)(Vh + (size_t)row0 * KVDIM + col) = pack2h(a00, a01);
                    *(uint32_t*)(Vh + (size_t)row1 * KVDIM + col) = pack2h(a10, a11);
                } else {
                    int col = (region == 0) ? n0 : (n0 - QDIM);
                    int p = (col & (HD - 1)) >> 1;
                    float c0 = cosb[row0 * (HD / 2) + p], s0 = sinb[row0 * (HD / 2) + p];
                    float c1 = cosb[row1 * (HD / 2) + p], s1 = sinb[row1 * (HD / 2) + p];
                    float r00 = a00 * c0 - a01 * s0, r01 = a00 * s0 + a01 * c0;
                    float r10 = a10 * c1 - a11 * s1, r11 = a10 * s1 + a11 * c1;
                    if (region == 0) {
                        r00 *= ATT_SCALE; r01 *= ATT_SCALE;
                        r10 *= ATT_SCALE; r11 *= ATT_SCALE;
                        uint32_t hi, lo;
                        split_pack(r00, r01, hi, lo);
                        *(uint32_t*)(Qh + (size_t)row0 * QDIM + col) = hi;
                        *(uint32_t*)(Ql + (size_t)row0 * QDIM + col) = lo;
                        split_pack(r10, r11, hi, lo);
                        *(uint32_t*)(Qh + (size_t)row1 * QDIM + col) = hi;
                        *(uint32_t*)(Ql + (size_t)row1 * QDIM + col) = lo;
                    } else {
                        *(uint32_t*)(Kh + (size_t)row0 * KVDIM + col) = pack2h(r00, r01);
                        *(uint32_t*)(Kh + (size_t)row1 * KVDIM + col) = pack2h(r10, r11);
                    }
                }
            }
        }
    }
}

// ---------------------------------------------------------------------------
// Flash attention, fp16: S = (Qh+Ql)*Kh^T, O += Ph*Vh (P lo-term dropped).
// Writes [hi|lo] K-concat split output directly (feeds WO GEMM).
// ---------------------------------------------------------------------------
#define PDD 136
#define ATT_SMEM ((2 * 128 * PDD + 2 * 2 * 64 * PDD) * 2)

__global__ __launch_bounds__(256, 1) void attn_mma_kernel(
    const __half* __restrict__ Qh, const __half* __restrict__ Ql,
    const __half* __restrict__ Kh, const __half* __restrict__ Vh,
    __half* __restrict__ OS)
{
    extern __shared__ __half sm[];
    __half* sQh = sm;
    __half* sQl = sQh + 128 * PDD;
    __half* sKV = sQl + 128 * PDD;

    const int tid  = threadIdx.x;
    const int lane = tid & 31;
    const int w    = tid >> 5;
    const int q0   = blockIdx.x * 64;
    const int kvh  = blockIdx.y >> 1;
    const int h0   = kvh * 4 + (blockIdx.y & 1) * 2;

    const int warp_row = w * 16;
    const int s_row0 = q0 + (warp_row & 63) + (lane >> 2);
    const int s_row1 = s_row0 + 8;
    const int h_out  = h0 + (warp_row >> 6);

#pragma unroll
    for (int i = 0; i < 8; i++) {
        int id = tid + i * 256;
        int r = id >> 4, c8 = (id & 15) * 8;
        int s = q0 + (r & 63), h = h0 + (r >> 6);
        size_t g = ((size_t)s * NH + h) * HD + c8;
        cp_async16(smem_u32(sQh + r * PDD + c8), Qh + g);
        cp_async16(smem_u32(sQl + r * PDD + c8), Ql + g);
    }
    asm volatile("cp.async.commit_group;\n");

    float m0 = -1e30f, m1 = -1e30f, l0 = 0.f, l1 = 0.f;
    float o_acc[16][4];
#pragma unroll
    for (int i = 0; i < 16; i++)
#pragma unroll
        for (int r = 0; r < 4; r++) o_acc[i][r] = 0.f;

    int jlo = q0 - (WINDOW - 1); if (jlo < 0) jlo = 0;
    const int t0 = jlo >> 6, t1 = (q0 + 63) >> 6;

    auto load_kv = [&](int kt, int buf) {
        __half* b = sKV + buf * 2 * 64 * PDD;
        int kt0 = kt << 6;
#pragma unroll
        for (int i = 0; i < 4; i++) {
            int id = tid + i * 256;
            int r = id >> 4, c8 = (id & 15) * 8;
            size_t g = ((size_t)(kt0 + r) * NKV + kvh) * HD + c8;
            cp_async16(smem_u32(b + r * PDD + c8), Kh + g);
            cp_async16(smem_u32(b + 64 * PDD + r * PDD + c8), Vh + g);
        }
        asm volatile("cp.async.commit_group;\n");
    };

    load_kv(t0, 0);

    for (int kt = t0; kt <= t1; kt++) {
        const int buf = (kt - t0) & 1;
        const int kt0 = kt << 6;
        if (kt + 1 <= t1) {
            load_kv(kt + 1, buf ^ 1);
            asm volatile("cp.async.wait_group 1;\n");
        } else {
            asm volatile("cp.async.wait_group 0;\n");
        }
        __syncthreads();

        __half* bKh = sKV + buf * 2 * 64 * PDD;
        __half* bVh = bKh + 64 * PDD;

        float S[8][4];
#pragma unroll
        for (int nt = 0; nt < 8; nt++)
#pragma unroll
            for (int r = 0; r < 4; r++) S[nt][r] = 0.f;

#pragma unroll
        for (int pass = 0; pass < 2; pass++) {
            const __half* Asrc = pass ? sQl : sQh;
#pragma unroll
            for (int ks = 0; ks < 8; ks++) {
                uint32_t a[4];
                ldsm4(a, smem_u32(Asrc + (warp_row + (lane & 15)) * PDD
                                        + ks * 16 + (lane >> 4) * 8));
#pragma unroll
                for (int n2 = 0; n2 < 4; n2++) {
                    int row = n2 * 16 + ((lane >> 4) & 1) * 8 + (lane & 7);
                    int col = ks * 16 + ((lane >> 3) & 1) * 8;
                    uint32_t b4[4];
                    ldsm4(b4, smem_u32(bKh + row * PDD + col));
                    mma16816(S[n2 * 2],     a, b4);
                    mma16816(S[n2 * 2 + 1], a, b4 + 2);
                }
            }
        }

        bool edge = (kt0 + 63 > q0) || (kt0 < q0 + 63 - (WINDOW - 1));
        if (edge) {
#pragma unroll
            for (int nt = 0; nt < 8; nt++) {
                int jc = kt0 + nt * 8 + (lane & 3) * 2;
#pragma unroll
                for (int e = 0; e < 4; e++) {
                    int j = jc + (e & 1);
                    int s = (e < 2) ? s_row0 : s_row1;
                    if (!((j <= s) && (s - j < WINDOW))) S[nt][e] = -1e30f;
                }
            }
        }

        float mx0 = -1e30f, mx1 = -1e30f;
#pragma unroll
        for (int nt = 0; nt < 8; nt++) {
            mx0 = fmaxf(mx0, fmaxf(S[nt][0], S[nt][1]));
            mx1 = fmaxf(mx1, fmaxf(S[nt][2], S[nt][3]));
        }
#pragma unroll
        for (int off = 1; off <= 2; off <<= 1) {
            mx0 = fmaxf(mx0, __shfl_xor_sync(0xffffffffu, mx0, off));
            mx1 = fmaxf(mx1, __shfl_xor_sync(0xffffffffu, mx1, off));
        }
        float mn0 = fmaxf(m0, mx0), mn1 = fmaxf(m1, mx1);
        float al0 = __expf(m0 - mn0), al1 = __expf(m1 - mn1);
        m0 = mn0; m1 = mn1;

        float sum0 = 0.f, sum1 = 0.f;
        uint32_t phi[4][4];
#pragma unroll
        for (int j2 = 0; j2 < 4; j2++) {
            float p00 = __expf(S[2 * j2][0] - mn0);
            float p01 = __expf(S[2 * j2][1] - mn0);
            float p02 = __expf(S[2 * j2][2] - mn1);
            float p03 = __expf(S[2 * j2][3] - mn1);
            float p10 = __expf(S[2 * j2 + 1][0] - mn0);
            float p11 = __expf(S[2 * j2 + 1][1] - mn0);
            float p12 = __expf(S[2 * j2 + 1][2] - mn1);
            float p13 = __expf(S[2 * j2 + 1][3] - mn1);
            sum0 += p00 + p01 + p10 + p11;
            sum1 += p02 + p03 + p12 + p13;
            phi[j2][0] = pack2h(p00, p01);
            phi[j2][1] = pack2h(p02, p03);
            phi[j2][2] = pack2h(p10, p11);
            phi[j2][3] = pack2h(p12, p13);
        }
#pragma unroll
        for (int off = 1; off <= 2; off <<= 1) {
            sum0 += __shfl_xor_sync(0xffffffffu, sum0, off);
            sum1 += __shfl_xor_sync(0xffffffffu, sum1, off);
        }
        l0 = l0 * al0 + sum0;
        l1 = l1 * al1 + sum1;

#pragma unroll
        for (int i = 0; i < 16; i++) {
            o_acc[i][0] *= al0; o_acc[i][1] *= al0;
            o_acc[i][2] *= al1; o_acc[i][3] *= al1;
        }

#pragma unroll
        for (int j2 = 0; j2 < 4; j2++) {
            int row = j2 * 16 + ((lane >> 3) & 1) * 8 + (lane & 7);
#pragma unroll
            for (int d2 = 0; d2 < 8; d2++) {
                int col = d2 * 16 + ((lane >> 4) & 1) * 8;
                uint32_t bh[4];
                ldsm4t(bh, smem_u32(bVh + row * PDD + col));
                mma16816(o_acc[d2 * 2],     phi[j2], bh);
                mma16816(o_acc[d2 * 2 + 1], phi[j2], bh + 2);
            }
        }
        __syncthreads();
    }

    float inv0 = 1.0f / l0, inv1 = 1.0f / l1;
#pragma unroll
    for (int d2 = 0; d2 < 16; d2++) {
        int d = d2 * 8 + (lane & 3) * 2;
        uint32_t hi, lo;
        split_pack(o_acc[d2][0] * inv0, o_acc[d2][1] * inv0, hi, lo);
        size_t b0 = (size_t)s_row0 * K2 + h_out * HD + d;
        *(uint32_t*)(OS + b0)        = hi;
        *(uint32_t*)(OS + b0 + QDIM) = lo;
        split_pack(o_acc[d2][2] * inv1, o_acc[d2][3] * inv1, hi, lo);
        size_t b1 = (size_t)s_row1 * K2 + h_out * HD + d;
        *(uint32_t*)(OS + b1)        = hi;
        *(uint32_t*)(OS + b1 + QDIM) = lo;
    }
}

// ---------------------------------------------------------------------------
// Launch
// ---------------------------------------------------------------------------
extern "C" void kernel_launch(void* const* d_in, const int* in_sizes, int n_in,
                              void* d_out, int out_size)
{
    const float* x    = (const float*)d_in[0];
    const float* wq   = (const float*)d_in[1];
    const float* wk   = (const float*)d_in[2];
    const float* wv   = (const float*)d_in[3];
    const float* wo   = (const float*)d_in[4];
    const float* cosb = (const float*)d_in[5];
    const float* sinb = (const float*)d_in[6];
    float* out = (float*)d_out;

    __half *xs, *os, *wqkvs, *wos, *qh, *ql, *kh, *vh;
    cudaGetSymbolAddress((void**)&xs, g_xs);
    cudaGetSymbolAddress((void**)&os, g_os);
    cudaGetSymbolAddress((void**)&wqkvs, g_wqkvs);
    cudaGetSymbolAddress((void**)&wos, g_wos);
    cudaGetSymbolAddress((void**)&qh, g_qh);
    cudaGetSymbolAddress((void**)&ql, g_ql);
    cudaGetSymbolAddress((void**)&kh, g_kh);
    cudaGetSymbolAddress((void**)&vh, g_vh);

    cudaFuncSetAttribute(gemm_fp16_nt<0>,
                         cudaFuncAttributeMaxDynamicSharedMemorySize, GEMM_SMEM);
    cudaFuncSetAttribute(gemm_fp16_nt<1>,
                         cudaFuncAttributeMaxDynamicSharedMemorySize, GEMM_SMEM);
    cudaFuncSetAttribute(attn_mma_kernel,
                         cudaFuncAttributeMaxDynamicSharedMemorySize, ATT_SMEM);

    const int T = 256;
    convert_split8<<<(SEQ * DIM / 8 + T - 1) / T, T>>>(x, xs, SEQ, DIM, 1);
    convert_split8<<<(QDIM * DIM / 8 + T - 1) / T, T>>>(wq, wqkvs, QDIM, DIM, 0);
    convert_split8<<<(KVDIM * DIM / 8 + T - 1) / T, T>>>(
        wk, wqkvs + (size_t)QDIM * K2, KVDIM, DIM, 0);
    convert_split8<<<(KVDIM * DIM / 8 + T - 1) / T, T>>>(
        wv, wqkvs + (size_t)(QDIM + KVDIM) * K2, KVDIM, DIM, 0);
    convert_split8<<<(DIM * QDIM / 8 + T - 1) / T, T>>>(wo, wos, DIM, QDIM, 0);

    // fused QKV projection + rope + scale + split epilogue
    {
        dim3 g(QKVDIM / BN, SEQ / BM);
        gemm_fp16_nt<1><<<g, 256, GEMM_SMEM>>>(
            xs, wqkvs, nullptr, qh, ql, kh, vh, cosb, sinb, SEQ, QKVDIM, K2);
    }

    // flash attention (emits [hi|lo] split output)
    {
        dim3 ga(SEQ / 64, NKV * 2);
        attn_mma_kernel<<<ga, 256, ATT_SMEM>>>(qh, ql, kh, vh, os);
    }

    // output projection
    {
        dim3 g(DIM / BN, SEQ / BM);
        gemm_fp16_nt<0><<<g, 256, GEMM_SMEM>>>(
            os, wos, out, nullptr, nullptr, nullptr, nullptr, nullptr, nullptr,
            SEQ, DIM, K2);
    }
}

// round 8
// speedup vs baseline: 18.2226x; 1.7442x over previous
#include <cuda_runtime.h>
#include <cuda_fp16.h>
#include <math.h>
#include <stdint.h>

#define SEQ     2048
#define DIM     4096
#define NH      32
#define NKV     8
#define HD      128
#define WINDOW  1024
#define QDIM    (NH * HD)            // 4096
#define KVDIM   (NKV * HD)           // 1024
#define QKVDIM  (QDIM + 2 * KVDIM)   // 6144
#define ATT_SCALE 0.08838834764831845f

// ---------------------------------------------------------------------------
// Scratch (plain fp16 operands; activation splits only inside attention)
// ---------------------------------------------------------------------------
__device__ __align__(256) __half g_xs   [SEQ * DIM];
__device__ __align__(256) __half g_os   [SEQ * QDIM];
__device__ __align__(256) __half g_wqkvs[QKVDIM * DIM];
__device__ __align__(256) __half g_wos  [DIM * QDIM];

__device__ __align__(256) __half g_qh[SEQ * QDIM], g_ql[SEQ * QDIM];
__device__ __align__(256) __half g_kh[SEQ * KVDIM];
__device__ __align__(256) __half g_vh[SEQ * KVDIM];

// ---------------------------------------------------------------------------
// helpers
// ---------------------------------------------------------------------------
__device__ __forceinline__ uint32_t smem_u32(const void* p) {
    return (uint32_t)__cvta_generic_to_shared(p);
}
__device__ __forceinline__ void cp_async16(uint32_t dst, const void* src) {
    asm volatile("cp.async.cg.shared.global [%0], [%1], 16;\n" :: "r"(dst), "l"(src));
}
__device__ __forceinline__ void mma16816(float* c, const uint32_t* a, const uint32_t* b) {
    asm volatile(
        "mma.sync.aligned.m16n8k16.row.col.f32.f16.f16.f32 "
        "{%0,%1,%2,%3}, {%4,%5,%6,%7}, {%8,%9}, {%0,%1,%2,%3};\n"
        : "+f"(c[0]), "+f"(c[1]), "+f"(c[2]), "+f"(c[3])
        : "r"(a[0]), "r"(a[1]), "r"(a[2]), "r"(a[3]), "r"(b[0]), "r"(b[1]));
}
__device__ __forceinline__ void ldsm4(uint32_t* r, uint32_t addr) {
    asm volatile("ldmatrix.sync.aligned.m8n8.x4.shared.b16 {%0,%1,%2,%3}, [%4];\n"
        : "=r"(r[0]), "=r"(r[1]), "=r"(r[2]), "=r"(r[3]) : "r"(addr));
}
__device__ __forceinline__ void ldsm4t(uint32_t* r, uint32_t addr) {
    asm volatile("ldmatrix.sync.aligned.m8n8.x4.trans.shared.b16 {%0,%1,%2,%3}, [%4];\n"
        : "=r"(r[0]), "=r"(r[1]), "=r"(r[2]), "=r"(r[3]) : "r"(addr));
}
__device__ __forceinline__ uint32_t pack2h(float p0, float p1) {
    __half h0 = __float2half_rn(p0), h1 = __float2half_rn(p1);
    return ((uint32_t)*(uint16_t*)&h1 << 16) | (uint32_t)*(uint16_t*)&h0;
}
__device__ __forceinline__ void split_pack(float p0, float p1, uint32_t& hi, uint32_t& lo) {
    __half h0 = __float2half_rn(p0), h1 = __float2half_rn(p1);
    hi = ((uint32_t)*(uint16_t*)&h1 << 16) | (uint32_t)*(uint16_t*)&h0;
    __half l0 = __float2half_rn(p0 - __half2float(h0));
    __half l1 = __float2half_rn(p1 - __half2float(h1));
    lo = ((uint32_t)*(uint16_t*)&l1 << 16) | (uint32_t)*(uint16_t*)&l0;
}

// ---------------------------------------------------------------------------
// flat fp32 -> fp16 conversion, 8 elems/thread (16B stores)
// ---------------------------------------------------------------------------
__global__ void cvt8(const float* __restrict__ src, __half* __restrict__ dst, int n8)
{
    int idx = blockIdx.x * blockDim.x + threadIdx.x;
    if (idx >= n8) return;
    const float* s = src + (size_t)idx * 8;
    float4 a0 = *(const float4*)(s);
    float4 a1 = *(const float4*)(s + 4);
    uint4 o;
    o.x = pack2h(a0.x, a0.y);
    o.y = pack2h(a0.z, a0.w);
    o.z = pack2h(a1.x, a1.y);
    o.w = pack2h(a1.z, a1.w);
    *(uint4*)(dst + (size_t)idx * 8) = o;
}

// ---------------------------------------------------------------------------
// fp16 NT GEMM, 4-stage cp.async ring. 128x128x32 tiles, 8 warps (2Mx4N),
// warp tile 64x32. EPI=0: plain fp32 C. EPI=1: fused rope/scale/split
// epilogue writing qh/ql/kh/vh (QKV projection).
// ---------------------------------------------------------------------------
#define BM 128
#define BN 128
#define BK 32
#define KP 40
#define NST 4
#define STG_H ((BM + BN) * KP)
#define GEMM_SMEM (NST * STG_H * 2)   // 81920 bytes

template <int EPI>
__global__ __launch_bounds__(256, 2) void gemm_fp16_nt(
    const __half* __restrict__ A, const __half* __restrict__ B,
    float* __restrict__ C,
    __half* __restrict__ Qh, __half* __restrict__ Ql,
    __half* __restrict__ Kh, __half* __restrict__ Vh,
    const float* __restrict__ cosb, const float* __restrict__ sinb,
    int M, int N, int K)
{
    extern __shared__ __half smg[];

    const int tid  = threadIdx.x;
    const int lane = tid & 31;
    const int w    = tid >> 5;
    const int bm   = blockIdx.y * BM;
    const int bn   = blockIdx.x * BN;
    const int warp_m = (w & 1) * 64;
    const int warp_n = (w >> 1) * 32;

    float acc[4][4][4];
#pragma unroll
    for (int i = 0; i < 4; i++)
#pragma unroll
        for (int j = 0; j < 4; j++)
#pragma unroll
            for (int r = 0; r < 4; r++) acc[i][j][r] = 0.0f;

    const int KB = K / BK;

    auto load_stage = [&](int kb) {
        __half* As = smg + (kb & (NST - 1)) * STG_H;
        __half* Bs = As + BM * KP;
        int k0 = kb * BK;
#pragma unroll
        for (int i = 0; i < 2; i++) {
            int id  = tid + i * 256;
            int row = id >> 2;
            int c8  = (id & 3) * 8;
            cp_async16(smem_u32(As + row * KP + c8),
                       A + (size_t)(bm + row) * K + k0 + c8);
            cp_async16(smem_u32(Bs + row * KP + c8),
                       B + (size_t)(bn + row) * K + k0 + c8);
        }
        asm volatile("cp.async.commit_group;\n");
    };

    load_stage(0);
    load_stage(1);
    load_stage(2);

    for (int kb = 0; kb < KB; kb++) {
        asm volatile("cp.async.wait_group 2;\n");
        __syncthreads();
        if (kb + 3 < KB) {
            load_stage(kb + 3);
        } else {
            asm volatile("cp.async.commit_group;\n");
        }

        __half* As = smg + (kb & (NST - 1)) * STG_H;
        __half* Bs = As + BM * KP;

#pragma unroll
        for (int ks = 0; ks < 2; ks++) {
            uint32_t a_frag[4][4];
#pragma unroll
            for (int mt = 0; mt < 4; mt++) {
                uint32_t addr = smem_u32(
                    As + (warp_m + mt * 16 + (lane & 15)) * KP
                       + ks * 16 + (lane >> 4) * 8);
                ldsm4(a_frag[mt], addr);
            }
            uint32_t b_frag[4][2];
#pragma unroll
            for (int half = 0; half < 2; half++) {
                int nt0 = half * 2;
                int row = warp_n + nt0 * 8 + ((lane >> 4) & 1) * 8 + (lane & 7);
                int col = ks * 16 + ((lane >> 3) & 1) * 8;
                uint32_t r4[4];
                ldsm4(r4, smem_u32(Bs + row * KP + col));
                b_frag[nt0][0] = r4[0]; b_frag[nt0][1] = r4[1];
                b_frag[nt0 + 1][0] = r4[2]; b_frag[nt0 + 1][1] = r4[3];
            }
#pragma unroll
            for (int mt = 0; mt < 4; mt++)
#pragma unroll
                for (int nt = 0; nt < 4; nt++)
                    mma16816(acc[mt][nt], a_frag[mt], b_frag[nt]);
        }
    }

    const int g   = lane >> 2;
    const int tig = lane & 3;

    if (EPI == 0) {
#pragma unroll
        for (int mt = 0; mt < 4; mt++) {
#pragma unroll
            for (int nt = 0; nt < 4; nt++) {
                float* c0 = C + (size_t)(bm + warp_m + mt * 16 + g) * N
                              + bn + warp_n + nt * 8 + tig * 2;
                float* c1 = c0 + 8 * (size_t)N;
                *(float2*)c0 = make_float2(acc[mt][nt][0], acc[mt][nt][1]);
                *(float2*)c1 = make_float2(acc[mt][nt][2], acc[mt][nt][3]);
            }
        }
    } else {
        // region is uniform per block (BN=128 divides region boundaries)
        const int region = (bn < QDIM) ? 0 : ((bn < QDIM + KVDIM) ? 1 : 2);
#pragma unroll
        for (int mt = 0; mt < 4; mt++) {
            int row0 = bm + warp_m + mt * 16 + g;
            int row1 = row0 + 8;
#pragma unroll
            for (int nt = 0; nt < 4; nt++) {
                int n0 = bn + warp_n + nt * 8 + tig * 2;
                float a00 = acc[mt][nt][0], a01 = acc[mt][nt][1];
                float a10 = acc[mt][nt][2], a11 = acc[mt][nt][3];
                if (region == 2) {
                    int col = n0 - (QDIM + KVDIM);
                    *(uint32_t*)(Vh + (size_t)row0 * KVDIM + col) = pack2h(a00, a01);
                    *(uint32_t*)(Vh + (size_t)row1 * KVDIM + col) = pack2h(a10, a11);
                } else {
                    int col = (region == 0) ? n0 : (n0 - QDIM);
                    int p = (col & (HD - 1)) >> 1;
                    float c0 = cosb[row0 * (HD / 2) + p], s0 = sinb[row0 * (HD / 2) + p];
                    float c1 = cosb[row1 * (HD / 2) + p], s1 = sinb[row1 * (HD / 2) + p];
                    float r00 = a00 * c0 - a01 * s0, r01 = a00 * s0 + a01 * c0;
                    float r10 = a10 * c1 - a11 * s1, r11 = a10 * s1 + a11 * c1;
                    if (region == 0) {
                        r00 *= ATT_SCALE; r01 *= ATT_SCALE;
                        r10 *= ATT_SCALE; r11 *= ATT_SCALE;
                        uint32_t hi, lo;
                        split_pack(r00, r01, hi, lo);
                        *(uint32_t*)(Qh + (size_t)row0 * QDIM + col) = hi;
                        *(uint32_t*)(Ql + (size_t)row0 * QDIM + col) = lo;
                        split_pack(r10, r11, hi, lo);
                        *(uint32_t*)(Qh + (size_t)row1 * QDIM + col) = hi;
                        *(uint32_t*)(Ql + (size_t)row1 * QDIM + col) = lo;
                    } else {
                        *(uint32_t*)(Kh + (size_t)row0 * KVDIM + col) = pack2h(r00, r01);
                        *(uint32_t*)(Kh + (size_t)row1 * KVDIM + col) = pack2h(r10, r11);
                    }
                }
            }
        }
    }
}

// ---------------------------------------------------------------------------
// Flash attention, fp16: S = (Qh+Ql)*Kh^T, O += Ph*Vh.
// Writes plain fp16 output (feeds hi-only WO GEMM).
// ---------------------------------------------------------------------------
#define PDD 136
#define ATT_SMEM ((2 * 128 * PDD + 2 * 2 * 64 * PDD) * 2)

__global__ __launch_bounds__(256, 1) void attn_mma_kernel(
    const __half* __restrict__ Qh, const __half* __restrict__ Ql,
    const __half* __restrict__ Kh, const __half* __restrict__ Vh,
    __half* __restrict__ OS)
{
    extern __shared__ __half sm[];
    __half* sQh = sm;
    __half* sQl = sQh + 128 * PDD;
    __half* sKV = sQl + 128 * PDD;

    const int tid  = threadIdx.x;
    const int lane = tid & 31;
    const int w    = tid >> 5;
    const int q0   = blockIdx.x * 64;
    const int kvh  = blockIdx.y >> 1;
    const int h0   = kvh * 4 + (blockIdx.y & 1) * 2;

    const int warp_row = w * 16;
    const int s_row0 = q0 + (warp_row & 63) + (lane >> 2);
    const int s_row1 = s_row0 + 8;
    const int h_out  = h0 + (warp_row >> 6);

#pragma unroll
    for (int i = 0; i < 8; i++) {
        int id = tid + i * 256;
        int r = id >> 4, c8 = (id & 15) * 8;
        int s = q0 + (r & 63), h = h0 + (r >> 6);
        size_t g = ((size_t)s * NH + h) * HD + c8;
        cp_async16(smem_u32(sQh + r * PDD + c8), Qh + g);
        cp_async16(smem_u32(sQl + r * PDD + c8), Ql + g);
    }
    asm volatile("cp.async.commit_group;\n");

    float m0 = -1e30f, m1 = -1e30f, l0 = 0.f, l1 = 0.f;
    float o_acc[16][4];
#pragma unroll
    for (int i = 0; i < 16; i++)
#pragma unroll
        for (int r = 0; r < 4; r++) o_acc[i][r] = 0.f;

    int jlo = q0 - (WINDOW - 1); if (jlo < 0) jlo = 0;
    const int t0 = jlo >> 6, t1 = (q0 + 63) >> 6;

    auto load_kv = [&](int kt, int buf) {
        __half* b = sKV + buf * 2 * 64 * PDD;
        int kt0 = kt << 6;
#pragma unroll
        for (int i = 0; i < 4; i++) {
            int id = tid + i * 256;
            int r = id >> 4, c8 = (id & 15) * 8;
            size_t g = ((size_t)(kt0 + r) * NKV + kvh) * HD + c8;
            cp_async16(smem_u32(b + r * PDD + c8), Kh + g);
            cp_async16(smem_u32(b + 64 * PDD + r * PDD + c8), Vh + g);
        }
        asm volatile("cp.async.commit_group;\n");
    };

    load_kv(t0, 0);

    for (int kt = t0; kt <= t1; kt++) {
        const int buf = (kt - t0) & 1;
        const int kt0 = kt << 6;
        if (kt + 1 <= t1) {
            load_kv(kt + 1, buf ^ 1);
            asm volatile("cp.async.wait_group 1;\n");
        } else {
            asm volatile("cp.async.wait_group 0;\n");
        }
        __syncthreads();

        __half* bKh = sKV + buf * 2 * 64 * PDD;
        __half* bVh = bKh + 64 * PDD;

        float S[8][4];
#pragma unroll
        for (int nt = 0; nt < 8; nt++)
#pragma unroll
            for (int r = 0; r < 4; r++) S[nt][r] = 0.f;

#pragma unroll
        for (int pass = 0; pass < 2; pass++) {
            const __half* Asrc = pass ? sQl : sQh;
#pragma unroll
            for (int ks = 0; ks < 8; ks++) {
                uint32_t a[4];
                ldsm4(a, smem_u32(Asrc + (warp_row + (lane & 15)) * PDD
                                        + ks * 16 + (lane >> 4) * 8));
#pragma unroll
                for (int n2 = 0; n2 < 4; n2++) {
                    int row = n2 * 16 + ((lane >> 4) & 1) * 8 + (lane & 7);
                    int col = ks * 16 + ((lane >> 3) & 1) * 8;
                    uint32_t b4[4];
                    ldsm4(b4, smem_u32(bKh + row * PDD + col));
                    mma16816(S[n2 * 2],     a, b4);
                    mma16816(S[n2 * 2 + 1], a, b4 + 2);
                }
            }
        }

        bool edge = (kt0 + 63 > q0) || (kt0 < q0 + 63 - (WINDOW - 1));
        if (edge) {
#pragma unroll
            for (int nt = 0; nt < 8; nt++) {
                int jc = kt0 + nt * 8 + (lane & 3) * 2;
#pragma unroll
                for (int e = 0; e < 4; e++) {
                    int j = jc + (e & 1);
                    int s = (e < 2) ? s_row0 : s_row1;
                    if (!((j <= s) && (s - j < WINDOW))) S[nt][e] = -1e30f;
                }
            }
        }

        float mx0 = -1e30f, mx1 = -1e30f;
#pragma unroll
        for (int nt = 0; nt < 8; nt++) {
            mx0 = fmaxf(mx0, fmaxf(S[nt][0], S[nt][1]));
            mx1 = fmaxf(mx1, fmaxf(S[nt][2], S[nt][3]));
        }
#pragma unroll
        for (int off = 1; off <= 2; off <<= 1) {
            mx0 = fmaxf(mx0, __shfl_xor_sync(0xffffffffu, mx0, off));
            mx1 = fmaxf(mx1, __shfl_xor_sync(0xffffffffu, mx1, off));
        }
        float mn0 = fmaxf(m0, mx0), mn1 = fmaxf(m1, mx1);
        float al0 = __expf(m0 - mn0), al1 = __expf(m1 - mn1);
        m0 = mn0; m1 = mn1;

        float sum0 = 0.f, sum1 = 0.f;
        uint32_t phi[4][4];
#pragma unroll
        for (int j2 = 0; j2 < 4; j2++) {
            float p00 = __expf(S[2 * j2][0] - mn0);
            float p01 = __expf(S[2 * j2][1] - mn0);
            float p02 = __expf(S[2 * j2][2] - mn1);
            float p03 = __expf(S[2 * j2][3] - mn1);
            float p10 = __expf(S[2 * j2 + 1][0] - mn0);
            float p11 = __expf(S[2 * j2 + 1][1] - mn0);
            float p12 = __expf(S[2 * j2 + 1][2] - mn1);
            float p13 = __expf(S[2 * j2 + 1][3] - mn1);
            sum0 += p00 + p01 + p10 + p11;
            sum1 += p02 + p03 + p12 + p13;
            phi[j2][0] = pack2h(p00, p01);
            phi[j2][1] = pack2h(p02, p03);
            phi[j2][2] = pack2h(p10, p11);
            phi[j2][3] = pack2h(p12, p13);
        }
#pragma unroll
        for (int off = 1; off <= 2; off <<= 1) {
            sum0 += __shfl_xor_sync(0xffffffffu, sum0, off);
            sum1 += __shfl_xor_sync(0xffffffffu, sum1, off);
        }
        l0 = l0 * al0 + sum0;
        l1 = l1 * al1 + sum1;

#pragma unroll
        for (int i = 0; i < 16; i++) {
            o_acc[i][0] *= al0; o_acc[i][1] *= al0;
            o_acc[i][2] *= al1; o_acc[i][3] *= al1;
        }

#pragma unroll
        for (int j2 = 0; j2 < 4; j2++) {
            int row = j2 * 16 + ((lane >> 3) & 1) * 8 + (lane & 7);
#pragma unroll
            for (int d2 = 0; d2 < 8; d2++) {
                int col = d2 * 16 + ((lane >> 4) & 1) * 8;
                uint32_t bh[4];
                ldsm4t(bh, smem_u32(bVh + row * PDD + col));
                mma16816(o_acc[d2 * 2],     phi[j2], bh);
                mma16816(o_acc[d2 * 2 + 1], phi[j2], bh + 2);
            }
        }
        __syncthreads();
    }

    // plain fp16 output
    float inv0 = 1.0f / l0, inv1 = 1.0f / l1;
#pragma unroll
    for (int d2 = 0; d2 < 16; d2++) {
        int d = d2 * 8 + (lane & 3) * 2;
        *(uint32_t*)(OS + (size_t)s_row0 * QDIM + h_out * HD + d) =
            pack2h(o_acc[d2][0] * inv0, o_acc[d2][1] * inv0);
        *(uint32_t*)(OS + (size_t)s_row1 * QDIM + h_out * HD + d) =
            pack2h(o_acc[d2][2] * inv1, o_acc[d2][3] * inv1);
    }
}

// ---------------------------------------------------------------------------
// Launch
// ---------------------------------------------------------------------------
extern "C" void kernel_launch(void* const* d_in, const int* in_sizes, int n_in,
                              void* d_out, int out_size)
{
    const float* x    = (const float*)d_in[0];
    const float* wq   = (const float*)d_in[1];
    const float* wk   = (const float*)d_in[2];
    const float* wv   = (const float*)d_in[3];
    const float* wo   = (const float*)d_in[4];
    const float* cosb = (const float*)d_in[5];
    const float* sinb = (const float*)d_in[6];
    float* out = (float*)d_out;

    __half *xs, *os, *wqkvs, *wos, *qh, *ql, *kh, *vh;
    cudaGetSymbolAddress((void**)&xs, g_xs);
    cudaGetSymbolAddress((void**)&os, g_os);
    cudaGetSymbolAddress((void**)&wqkvs, g_wqkvs);
    cudaGetSymbolAddress((void**)&wos, g_wos);
    cudaGetSymbolAddress((void**)&qh, g_qh);
    cudaGetSymbolAddress((void**)&ql, g_ql);
    cudaGetSymbolAddress((void**)&kh, g_kh);
    cudaGetSymbolAddress((void**)&vh, g_vh);

    cudaFuncSetAttribute(gemm_fp16_nt<0>,
                         cudaFuncAttributeMaxDynamicSharedMemorySize, GEMM_SMEM);
    cudaFuncSetAttribute(gemm_fp16_nt<1>,
                         cudaFuncAttributeMaxDynamicSharedMemorySize, GEMM_SMEM);
    cudaFuncSetAttribute(attn_mma_kernel,
                         cudaFuncAttributeMaxDynamicSharedMemorySize, ATT_SMEM);

    const int T = 256;
    cvt8<<<(SEQ * DIM / 8 + T - 1) / T, T>>>(x, xs, SEQ * DIM / 8);
    cvt8<<<(QDIM * DIM / 8 + T - 1) / T, T>>>(wq, wqkvs, QDIM * DIM / 8);
    cvt8<<<(KVDIM * DIM / 8 + T - 1) / T, T>>>(
        wk, wqkvs + (size_t)QDIM * DIM, KVDIM * DIM / 8);
    cvt8<<<(KVDIM * DIM / 8 + T - 1) / T, T>>>(
        wv, wqkvs + (size_t)(QDIM + KVDIM) * DIM, KVDIM * DIM / 8);
    cvt8<<<(DIM * QDIM / 8 + T - 1) / T, T>>>(wo, wos, DIM * QDIM / 8);

    // fused QKV projection + rope + scale + split epilogue (K = DIM)
    {
        dim3 g(QKVDIM / BN, SEQ / BM);
        gemm_fp16_nt<1><<<g, 256, GEMM_SMEM>>>(
            xs, wqkvs, nullptr, qh, ql, kh, vh, cosb, sinb, SEQ, QKVDIM, DIM);
    }

    // flash attention (plain fp16 output)
    {
        dim3 ga(SEQ / 64, NKV * 2);
        attn_mma_kernel<<<ga, 256, ATT_SMEM>>>(qh, ql, kh, vh, os);
    }

    // output projection (K = QDIM)
    {
        dim3 g(DIM / BN, SEQ / BM);
        gemm_fp16_nt<0><<<g, 256, GEMM_SMEM>>>(
            os, wos, out, nullptr, nullptr, nullptr, nullptr, nullptr, nullptr,
            SEQ, DIM, QDIM);
    }
}

// round 9
// speedup vs baseline: 18.7943x; 1.0314x over previous
#include <cuda_runtime.h>
#include <cuda_fp16.h>
#include <math.h>
#include <stdint.h>

#define SEQ     2048
#define DIM     4096
#define NH      32
#define NKV     8
#define HD      128
#define WINDOW  1024
#define QDIM    (NH * HD)            // 4096
#define KVDIM   (NKV * HD)           // 1024
#define QKVDIM  (QDIM + 2 * KVDIM)   // 6144
#define ATT_SCALE 0.08838834764831845f

// ---------------------------------------------------------------------------
// Scratch
// ---------------------------------------------------------------------------
__device__ __align__(256) __half g_xs   [SEQ * DIM];
__device__ __align__(256) __half g_os   [SEQ * QDIM];
__device__ __align__(256) __half g_wqkvs[QKVDIM * DIM];
__device__ __align__(256) __half g_wos  [DIM * QDIM];

__device__ __align__(256) __half g_qh[SEQ * QDIM], g_ql[SEQ * QDIM];
__device__ __align__(256) __half g_kh[SEQ * KVDIM];
__device__ __align__(256) __half g_vh[SEQ * KVDIM];

// ---------------------------------------------------------------------------
// helpers
// ---------------------------------------------------------------------------
__device__ __forceinline__ uint32_t smem_u32(const void* p) {
    return (uint32_t)__cvta_generic_to_shared(p);
}
__device__ __forceinline__ void cp_async16(uint32_t dst, const void* src) {
    asm volatile("cp.async.cg.shared.global [%0], [%1], 16;\n" :: "r"(dst), "l"(src));
}
__device__ __forceinline__ void mma16816(float* c, const uint32_t* a, const uint32_t* b) {
    asm volatile(
        "mma.sync.aligned.m16n8k16.row.col.f32.f16.f16.f32 "
        "{%0,%1,%2,%3}, {%4,%5,%6,%7}, {%8,%9}, {%0,%1,%2,%3};\n"
        : "+f"(c[0]), "+f"(c[1]), "+f"(c[2]), "+f"(c[3])
        : "r"(a[0]), "r"(a[1]), "r"(a[2]), "r"(a[3]), "r"(b[0]), "r"(b[1]));
}
__device__ __forceinline__ void ldsm4(uint32_t* r, uint32_t addr) {
    asm volatile("ldmatrix.sync.aligned.m8n8.x4.shared.b16 {%0,%1,%2,%3}, [%4];\n"
        : "=r"(r[0]), "=r"(r[1]), "=r"(r[2]), "=r"(r[3]) : "r"(addr));
}
__device__ __forceinline__ void ldsm4t(uint32_t* r, uint32_t addr) {
    asm volatile("ldmatrix.sync.aligned.m8n8.x4.trans.shared.b16 {%0,%1,%2,%3}, [%4];\n"
        : "=r"(r[0]), "=r"(r[1]), "=r"(r[2]), "=r"(r[3]) : "r"(addr));
}
__device__ __forceinline__ uint32_t pack2h(float p0, float p1) {
    __half h0 = __float2half_rn(p0), h1 = __float2half_rn(p1);
    return ((uint32_t)*(uint16_t*)&h1 << 16) | (uint32_t)*(uint16_t*)&h0;
}
__device__ __forceinline__ void split_pack(float p0, float p1, uint32_t& hi, uint32_t& lo) {
    __half h0 = __float2half_rn(p0), h1 = __float2half_rn(p1);
    hi = ((uint32_t)*(uint16_t*)&h1 << 16) | (uint32_t)*(uint16_t*)&h0;
    __half l0 = __float2half_rn(p0 - __half2float(h0));
    __half l1 = __float2half_rn(p1 - __half2float(h1));
    lo = ((uint32_t)*(uint16_t*)&l1 << 16) | (uint32_t)*(uint16_t*)&l0;
}

// ---------------------------------------------------------------------------
// Merged fp32 -> fp16 conversion: one kernel, 16 elems/thread (MLP=4).
// Regions (16-elem units): x | wq | wk | wv | wo
// ---------------------------------------------------------------------------
#define U_X    ((SEQ * DIM) / 16)           // 524288
#define U_WQ   ((QDIM * DIM) / 16)          // 1048576
#define U_WK   ((KVDIM * DIM) / 16)         // 262144
#define U_WQKV (U_WQ + 2 * U_WK)            // 1572864
#define U_WO   ((DIM * QDIM) / 16)          // 1048576
#define U_TOT  (U_X + U_WQKV + U_WO)        // 3145728

__global__ void cvt_all(const float* __restrict__ x,
                        const float* __restrict__ wq,
                        const float* __restrict__ wk,
                        const float* __restrict__ wv,
                        const float* __restrict__ wo,
                        __half* __restrict__ xs,
                        __half* __restrict__ wqkvs,
                        __half* __restrict__ wos)
{
    size_t u = (size_t)blockIdx.x * blockDim.x + threadIdx.x;
    if (u >= U_TOT) return;
    const float* s;
    __half* d;
    if (u < U_X) {
        s = x + u * 16; d = xs + u * 16;
    } else if (u < U_X + U_WQKV) {
        size_t v = u - U_X;
        d = wqkvs + v * 16;
        if (v < U_WQ)            s = wq + v * 16;
        else if (v < U_WQ + U_WK) s = wk + (v - U_WQ) * 16;
        else                      s = wv + (v - U_WQ - U_WK) * 16;
    } else {
        size_t v = u - U_X - U_WQKV;
        s = wo + v * 16; d = wos + v * 16;
    }
    float4 a0 = *(const float4*)(s);
    float4 a1 = *(const float4*)(s + 4);
    float4 a2 = *(const float4*)(s + 8);
    float4 a3 = *(const float4*)(s + 12);
    uint4 o0, o1;
    o0.x = pack2h(a0.x, a0.y); o0.y = pack2h(a0.z, a0.w);
    o0.z = pack2h(a1.x, a1.y); o0.w = pack2h(a1.z, a1.w);
    o1.x = pack2h(a2.x, a2.y); o1.y = pack2h(a2.z, a2.w);
    o1.z = pack2h(a3.x, a3.y); o1.w = pack2h(a3.z, a3.w);
    *(uint4*)(d)     = o0;
    *(uint4*)(d + 8) = o1;
}

// ---------------------------------------------------------------------------
// fp16 NT GEMM, 4-stage cp.async ring. 128x128x32 tiles, 8 warps (2Mx4N),
// warp tile 64x32. EPI=0: plain fp32 C. EPI=1: fused rope/scale/split
// epilogue writing qh/ql/kh/vh (QKV projection).
// ---------------------------------------------------------------------------
#define BM 128
#define BN 128
#define BK 32
#define KP 40
#define NST 4
#define STG_H ((BM + BN) * KP)
#define GEMM_SMEM (NST * STG_H * 2)   // 81920 bytes

template <int EPI>
__global__ __launch_bounds__(256, 2) void gemm_fp16_nt(
    const __half* __restrict__ A, const __half* __restrict__ B,
    float* __restrict__ C,
    __half* __restrict__ Qh, __half* __restrict__ Ql,
    __half* __restrict__ Kh, __half* __restrict__ Vh,
    const float* __restrict__ cosb, const float* __restrict__ sinb,
    int M, int N, int K)
{
    extern __shared__ __half smg[];

    const int tid  = threadIdx.x;
    const int lane = tid & 31;
    const int w    = tid >> 5;
    const int bm   = blockIdx.y * BM;
    const int bn   = blockIdx.x * BN;
    const int warp_m = (w & 1) * 64;
    const int warp_n = (w >> 1) * 32;

    float acc[4][4][4];
#pragma unroll
    for (int i = 0; i < 4; i++)
#pragma unroll
        for (int j = 0; j < 4; j++)
#pragma unroll
            for (int r = 0; r < 4; r++) acc[i][j][r] = 0.0f;

    const int KB = K / BK;

    auto load_stage = [&](int kb) {
        __half* As = smg + (kb & (NST - 1)) * STG_H;
        __half* Bs = As + BM * KP;
        int k0 = kb * BK;
#pragma unroll
        for (int i = 0; i < 2; i++) {
            int id  = tid + i * 256;
            int row = id >> 2;
            int c8  = (id & 3) * 8;
            cp_async16(smem_u32(As + row * KP + c8),
                       A + (size_t)(bm + row) * K + k0 + c8);
            cp_async16(smem_u32(Bs + row * KP + c8),
                       B + (size_t)(bn + row) * K + k0 + c8);
        }
        asm volatile("cp.async.commit_group;\n");
    };

    load_stage(0);
    load_stage(1);
    load_stage(2);

    for (int kb = 0; kb < KB; kb++) {
        asm volatile("cp.async.wait_group 2;\n");
        __syncthreads();
        if (kb + 3 < KB) {
            load_stage(kb + 3);
        } else {
            asm volatile("cp.async.commit_group;\n");
        }

        __half* As = smg + (kb & (NST - 1)) * STG_H;
        __half* Bs = As + BM * KP;

#pragma unroll
        for (int ks = 0; ks < 2; ks++) {
            uint32_t a_frag[4][4];
#pragma unroll
            for (int mt = 0; mt < 4; mt++) {
                uint32_t addr = smem_u32(
                    As + (warp_m + mt * 16 + (lane & 15)) * KP
                       + ks * 16 + (lane >> 4) * 8);
                ldsm4(a_frag[mt], addr);
            }
            uint32_t b_frag[4][2];
#pragma unroll
            for (int half = 0; half < 2; half++) {
                int nt0 = half * 2;
                int row = warp_n + nt0 * 8 + ((lane >> 4) & 1) * 8 + (lane & 7);
                int col = ks * 16 + ((lane >> 3) & 1) * 8;
                uint32_t r4[4];
                ldsm4(r4, smem_u32(Bs + row * KP + col));
                b_frag[nt0][0] = r4[0]; b_frag[nt0][1] = r4[1];
                b_frag[nt0 + 1][0] = r4[2]; b_frag[nt0 + 1][1] = r4[3];
            }
#pragma unroll
            for (int mt = 0; mt < 4; mt++)
#pragma unroll
                for (int nt = 0; nt < 4; nt++)
                    mma16816(acc[mt][nt], a_frag[mt], b_frag[nt]);
        }
    }

    const int g   = lane >> 2;
    const int tig = lane & 3;

    if (EPI == 0) {
#pragma unroll
        for (int mt = 0; mt < 4; mt++) {
#pragma unroll
            for (int nt = 0; nt < 4; nt++) {
                float* c0 = C + (size_t)(bm + warp_m + mt * 16 + g) * N
                              + bn + warp_n + nt * 8 + tig * 2;
                float* c1 = c0 + 8 * (size_t)N;
                *(float2*)c0 = make_float2(acc[mt][nt][0], acc[mt][nt][1]);
                *(float2*)c1 = make_float2(acc[mt][nt][2], acc[mt][nt][3]);
            }
        }
    } else {
        const int region = (bn < QDIM) ? 0 : ((bn < QDIM + KVDIM) ? 1 : 2);
#pragma unroll
        for (int mt = 0; mt < 4; mt++) {
            int row0 = bm + warp_m + mt * 16 + g;
            int row1 = row0 + 8;
#pragma unroll
            for (int nt = 0; nt < 4; nt++) {
                int n0 = bn + warp_n + nt * 8 + tig * 2;
                float a00 = acc[mt][nt][0], a01 = acc[mt][nt][1];
                float a10 = acc[mt][nt][2], a11 = acc[mt][nt][3];
                if (region == 2) {
                    int col = n0 - (QDIM + KVDIM);
                    *(uint32_t*)(Vh + (size_t)row0 * KVDIM + col) = pack2h(a00, a01);
                    *(uint32_t*)(Vh + (size_t)row1 * KVDIM + col) = pack2h(a10, a11);
                } else {
                    int col = (region == 0) ? n0 : (n0 - QDIM);
                    int p = (col & (HD - 1)) >> 1;
                    float c0 = cosb[row0 * (HD / 2) + p], s0 = sinb[row0 * (HD / 2) + p];
                    float c1 = cosb[row1 * (HD / 2) + p], s1 = sinb[row1 * (HD / 2) + p];
                    float r00 = a00 * c0 - a01 * s0, r01 = a00 * s0 + a01 * c0;
                    float r10 = a10 * c1 - a11 * s1, r11 = a10 * s1 + a11 * c1;
                    if (region == 0) {
                        r00 *= ATT_SCALE; r01 *= ATT_SCALE;
                        r10 *= ATT_SCALE; r11 *= ATT_SCALE;
                        uint32_t hi, lo;
                        split_pack(r00, r01, hi, lo);
                        *(uint32_t*)(Qh + (size_t)row0 * QDIM + col) = hi;
                        *(uint32_t*)(Ql + (size_t)row0 * QDIM + col) = lo;
                        split_pack(r10, r11, hi, lo);
                        *(uint32_t*)(Qh + (size_t)row1 * QDIM + col) = hi;
                        *(uint32_t*)(Ql + (size_t)row1 * QDIM + col) = lo;
                    } else {
                        *(uint32_t*)(Kh + (size_t)row0 * KVDIM + col) = pack2h(r00, r01);
                        *(uint32_t*)(Kh + (size_t)row1 * KVDIM + col) = pack2h(r10, r11);
                    }
                }
            }
        }
    }
}

// ---------------------------------------------------------------------------
// Flash attention, fp16: S = (Qh+Ql)*Kh^T (B fragments loaded once),
// O += Ph*Vh. Writes plain fp16 output.
// ---------------------------------------------------------------------------
#define PDD 136
#define ATT_SMEM ((2 * 128 * PDD + 2 * 2 * 64 * PDD) * 2)

__global__ __launch_bounds__(256, 1) void attn_mma_kernel(
    const __half* __restrict__ Qh, const __half* __restrict__ Ql,
    const __half* __restrict__ Kh, const __half* __restrict__ Vh,
    __half* __restrict__ OS)
{
    extern __shared__ __half sm[];
    __half* sQh = sm;
    __half* sQl = sQh + 128 * PDD;
    __half* sKV = sQl + 128 * PDD;

    const int tid  = threadIdx.x;
    const int lane = tid & 31;
    const int w    = tid >> 5;
    const int q0   = blockIdx.x * 64;
    const int kvh  = blockIdx.y >> 1;
    const int h0   = kvh * 4 + (blockIdx.y & 1) * 2;

    const int warp_row = w * 16;
    const int s_row0 = q0 + (warp_row & 63) + (lane >> 2);
    const int s_row1 = s_row0 + 8;
    const int h_out  = h0 + (warp_row >> 6);

#pragma unroll
    for (int i = 0; i < 8; i++) {
        int id = tid + i * 256;
        int r = id >> 4, c8 = (id & 15) * 8;
        int s = q0 + (r & 63), h = h0 + (r >> 6);
        size_t g = ((size_t)s * NH + h) * HD + c8;
        cp_async16(smem_u32(sQh + r * PDD + c8), Qh + g);
        cp_async16(smem_u32(sQl + r * PDD + c8), Ql + g);
    }
    asm volatile("cp.async.commit_group;\n");

    float m0 = -1e30f, m1 = -1e30f, l0 = 0.f, l1 = 0.f;
    float o_acc[16][4];
#pragma unroll
    for (int i = 0; i < 16; i++)
#pragma unroll
        for (int r = 0; r < 4; r++) o_acc[i][r] = 0.f;

    int jlo = q0 - (WINDOW - 1); if (jlo < 0) jlo = 0;
    const int t0 = jlo >> 6, t1 = (q0 + 63) >> 6;

    auto load_kv = [&](int kt, int buf) {
        __half* b = sKV + buf * 2 * 64 * PDD;
        int kt0 = kt << 6;
#pragma unroll
        for (int i = 0; i < 4; i++) {
            int id = tid + i * 256;
            int r = id >> 4, c8 = (id & 15) * 8;
            size_t g = ((size_t)(kt0 + r) * NKV + kvh) * HD + c8;
            cp_async16(smem_u32(b + r * PDD + c8), Kh + g);
            cp_async16(smem_u32(b + 64 * PDD + r * PDD + c8), Vh + g);
        }
        asm volatile("cp.async.commit_group;\n");
    };

    load_kv(t0, 0);

    for (int kt = t0; kt <= t1; kt++) {
        const int buf = (kt - t0) & 1;
        const int kt0 = kt << 6;
        if (kt + 1 <= t1) {
            load_kv(kt + 1, buf ^ 1);
            asm volatile("cp.async.wait_group 1;\n");
        } else {
            asm volatile("cp.async.wait_group 0;\n");
        }
        __syncthreads();

        __half* bKh = sKV + buf * 2 * 64 * PDD;
        __half* bVh = bKh + 64 * PDD;

        float S[8][4];
#pragma unroll
        for (int nt = 0; nt < 8; nt++)
#pragma unroll
            for (int r = 0; r < 4; r++) S[nt][r] = 0.f;

        // S = (Qh + Ql) * Kh^T; each K fragment loaded ONCE
#pragma unroll
        for (int ks = 0; ks < 8; ks++) {
            uint32_t a_hi[4], a_lo[4];
            uint32_t a_off = (warp_row + (lane & 15)) * PDD
                           + ks * 16 + (lane >> 4) * 8;
            ldsm4(a_hi, smem_u32(sQh + a_off));
            ldsm4(a_lo, smem_u32(sQl + a_off));
#pragma unroll
            for (int n2 = 0; n2 < 4; n2++) {
                int row = n2 * 16 + ((lane >> 4) & 1) * 8 + (lane & 7);
                int col = ks * 16 + ((lane >> 3) & 1) * 8;
                uint32_t b4[4];
                ldsm4(b4, smem_u32(bKh + row * PDD + col));
                mma16816(S[n2 * 2],     a_hi, b4);
                mma16816(S[n2 * 2 + 1], a_hi, b4 + 2);
                mma16816(S[n2 * 2],     a_lo, b4);
                mma16816(S[n2 * 2 + 1], a_lo, b4 + 2);
            }
        }

        bool edge = (kt0 + 63 > q0) || (kt0 < q0 + 63 - (WINDOW - 1));
        if (edge) {
#pragma unroll
            for (int nt = 0; nt < 8; nt++) {
                int jc = kt0 + nt * 8 + (lane & 3) * 2;
#pragma unroll
                for (int e = 0; e < 4; e++) {
                    int j = jc + (e & 1);
                    int s = (e < 2) ? s_row0 : s_row1;
                    if (!((j <= s) && (s - j < WINDOW))) S[nt][e] = -1e30f;
                }
            }
        }

        float mx0 = -1e30f, mx1 = -1e30f;
#pragma unroll
        for (int nt = 0; nt < 8; nt++) {
            mx0 = fmaxf(mx0, fmaxf(S[nt][0], S[nt][1]));
            mx1 = fmaxf(mx1, fmaxf(S[nt][2], S[nt][3]));
        }
#pragma unroll
        for (int off = 1; off <= 2; off <<= 1) {
            mx0 = fmaxf(mx0, __shfl_xor_sync(0xffffffffu, mx0, off));
            mx1 = fmaxf(mx1, __shfl_xor_sync(0xffffffffu, mx1, off));
        }
        float mn0 = fmaxf(m0, mx0), mn1 = fmaxf(m1, mx1);
        float al0 = __expf(m0 - mn0), al1 = __expf(m1 - mn1);
        m0 = mn0; m1 = mn1;

        float sum0 = 0.f, sum1 = 0.f;
        uint32_t phi[4][4];
#pragma unroll
        for (int j2 = 0; j2 < 4; j2++) {
            float p00 = __expf(S[2 * j2][0] - mn0);
            float p01 = __expf(S[2 * j2][1] - mn0);
            float p02 = __expf(S[2 * j2][2] - mn1);
            float p03 = __expf(S[2 * j2][3] - mn1);
            float p10 = __expf(S[2 * j2 + 1][0] - mn0);
            float p11 = __expf(S[2 * j2 + 1][1] - mn0);
            float p12 = __expf(S[2 * j2 + 1][2] - mn1);
            float p13 = __expf(S[2 * j2 + 1][3] - mn1);
            sum0 += p00 + p01 + p10 + p11;
            sum1 += p02 + p03 + p12 + p13;
            phi[j2][0] = pack2h(p00, p01);
            phi[j2][1] = pack2h(p02, p03);
            phi[j2][2] = pack2h(p10, p11);
            phi[j2][3] = pack2h(p12, p13);
        }
#pragma unroll
        for (int off = 1; off <= 2; off <<= 1) {
            sum0 += __shfl_xor_sync(0xffffffffu, sum0, off);
            sum1 += __shfl_xor_sync(0xffffffffu, sum1, off);
        }
        l0 = l0 * al0 + sum0;
        l1 = l1 * al1 + sum1;

#pragma unroll
        for (int i = 0; i < 16; i++) {
            o_acc[i][0] *= al0; o_acc[i][1] *= al0;
            o_acc[i][2] *= al1; o_acc[i][3] *= al1;
        }

#pragma unroll
        for (int j2 = 0; j2 < 4; j2++) {
            int row = j2 * 16 + ((lane >> 3) & 1) * 8 + (lane & 7);
#pragma unroll
            for (int d2 = 0; d2 < 8; d2++) {
                int col = d2 * 16 + ((lane >> 4) & 1) * 8;
                uint32_t bh[4];
                ldsm4t(bh, smem_u32(bVh + row * PDD + col));
                mma16816(o_acc[d2 * 2],     phi[j2], bh);
                mma16816(o_acc[d2 * 2 + 1], phi[j2], bh + 2);
            }
        }
        __syncthreads();
    }

    float inv0 = 1.0f / l0, inv1 = 1.0f / l1;
#pragma unroll
    for (int d2 = 0; d2 < 16; d2++) {
        int d = d2 * 8 + (lane & 3) * 2;
        *(uint32_t*)(OS + (size_t)s_row0 * QDIM + h_out * HD + d) =
            pack2h(o_acc[d2][0] * inv0, o_acc[d2][1] * inv0);
        *(uint32_t*)(OS + (size_t)s_row1 * QDIM + h_out * HD + d) =
            pack2h(o_acc[d2][2] * inv1, o_acc[d2][3] * inv1);
    }
}

// ---------------------------------------------------------------------------
// Launch
// ---------------------------------------------------------------------------
extern "C" void kernel_launch(void* const* d_in, const int* in_sizes, int n_in,
                              void* d_out, int out_size)
{
    const float* x    = (const float*)d_in[0];
    const float* wq   = (const float*)d_in[1];
    const float* wk   = (const float*)d_in[2];
    const float* wv   = (const float*)d_in[3];
    const float* wo   = (const float*)d_in[4];
    const float* cosb = (const float*)d_in[5];
    const float* sinb = (const float*)d_in[6];
    float* out = (float*)d_out;

    __half *xs, *os, *wqkvs, *wos, *qh, *ql, *kh, *vh;
    cudaGetSymbolAddress((void**)&xs, g_xs);
    cudaGetSymbolAddress((void**)&os, g_os);
    cudaGetSymbolAddress((void**)&wqkvs, g_wqkvs);
    cudaGetSymbolAddress((void**)&wos, g_wos);
    cudaGetSymbolAddress((void**)&qh, g_qh);
    cudaGetSymbolAddress((void**)&ql, g_ql);
    cudaGetSymbolAddress((void**)&kh, g_kh);
    cudaGetSymbolAddress((void**)&vh, g_vh);

    cudaFuncSetAttribute(gemm_fp16_nt<0>,
                         cudaFuncAttributeMaxDynamicSharedMemorySize, GEMM_SMEM);
    cudaFuncSetAttribute(gemm_fp16_nt<1>,
                         cudaFuncAttributeMaxDynamicSharedMemorySize, GEMM_SMEM);
    cudaFuncSetAttribute(attn_mma_kernel,
                         cudaFuncAttributeMaxDynamicSharedMemorySize, ATT_SMEM);

    // single merged conversion launch
    cvt_all<<<(U_TOT + 255) / 256, 256>>>(x, wq, wk, wv, wo, xs, wqkvs, wos);

    // fused QKV projection + rope + scale + split epilogue
    {
        dim3 g(QKVDIM / BN, SEQ / BM);
        gemm_fp16_nt<1><<<g, 256, GEMM_SMEM>>>(
            xs, wqkvs, nullptr, qh, ql, kh, vh, cosb, sinb, SEQ, QKVDIM, DIM);
    }

    // flash attention
    {
        dim3 ga(SEQ / 64, NKV * 2);
        attn_mma_kernel<<<ga, 256, ATT_SMEM>>>(qh, ql, kh, vh, os);
    }

    // output projection
    {
        dim3 g(DIM / BN, SEQ / BM);
        gemm_fp16_nt<0><<<g, 256, GEMM_SMEM>>>(
            os, wos, out, nullptr, nullptr, nullptr, nullptr, nullptr, nullptr,
            SEQ, DIM, QDIM);
    }
}